// round 2
// baseline (speedup 1.0000x reference)
#include <cuda_runtime.h>
#include <math.h>

#define D_MODEL 2048
#define NHEADS  16
#define DHEAD   128
#define SEQLEN  2048
#define BATCH   2
#define MROWS   (BATCH*SEQLEN)   // 4096

// ---------------- scratch (device globals; no allocation allowed) ----------------
__device__ float g_Q[BATCH*NHEADS*SEQLEN*DHEAD];   // [bh][s][128]
__device__ float g_K[BATCH*NHEADS*SEQLEN*DHEAD];
__device__ float g_V[BATCH*NHEADS*SEQLEN*DHEAD];
__device__ float g_A[BATCH*SEQLEN*D_MODEL];        // attn out, [b][s][d_model]
__device__ float g_cos[SEQLEN*(DHEAD/2)];
__device__ float g_sin[SEQLEN*(DHEAD/2)];

// ---------------- RoPE tables (double precision, closest to true values) ----------
__global__ void rope_table_kernel() {
    int idx = blockIdx.x * blockDim.x + threadIdx.x;   // 2048*64 threads
    int pos = idx >> 6;
    int p   = idx & 63;
    double freq = exp(-((double)(2 * p) / 128.0) * log(10000.0));
    double ang  = (double)pos * freq;
    g_cos[idx] = (float)cos(ang);
    g_sin[idx] = (float)sin(ang);
}

// ---------------- SGEMM: C = A[M,K] * W[N,K]^T + bias -----------------------------
// MODE: 0 = A := g_A (device global), plain row-major to outp
//       1 = V ([bh][s][d] layout), 2 = Q (layout + RoPE), 3 = K (layout + RoPE)
template<int MODE>
__global__ void __launch_bounds__(256, 2)
gemm_kernel(const float* __restrict__ Ain, const float* __restrict__ W,
            const float* __restrict__ bias, float* __restrict__ outp)
{
    __shared__ float As[16][128];
    __shared__ float Bs[16][128];

    // MODE 0 reads the attention output from the device global directly —
    // taking &g_A on the host is invalid (that was the R1 bug).
    const float* A = (MODE == 0) ? (const float*)g_A : Ain;

    const int tid = threadIdx.x;
    const int tx  = tid & 15, ty = tid >> 4;
    const int m0  = blockIdx.y * 128;
    const int n0  = blockIdx.x * 128;

    const int lrow = tid >> 1;        // 0..127
    const int lk0  = (tid & 1) * 2;   // float4 slot 0 or 2

    const float* aptr = A + (m0 + lrow) * 2048 + lk0 * 4;
    const float* bptr = W + (n0 + lrow) * 2048 + lk0 * 4;

    float4 pa0 = *(const float4*)(aptr);
    float4 pa1 = *(const float4*)(aptr + 4);
    float4 pb0 = *(const float4*)(bptr);
    float4 pb1 = *(const float4*)(bptr + 4);

    float acc[8][8];
    #pragma unroll
    for (int i = 0; i < 8; i++)
        #pragma unroll
        for (int j = 0; j < 8; j++) acc[i][j] = 0.f;

    for (int kt = 0; kt < 128; kt++) {
        __syncthreads();
        As[lk0*4+0][lrow] = pa0.x;  As[lk0*4+1][lrow] = pa0.y;
        As[lk0*4+2][lrow] = pa0.z;  As[lk0*4+3][lrow] = pa0.w;
        As[lk0*4+4][lrow] = pa1.x;  As[lk0*4+5][lrow] = pa1.y;
        As[lk0*4+6][lrow] = pa1.z;  As[lk0*4+7][lrow] = pa1.w;
        Bs[lk0*4+0][lrow] = pb0.x;  Bs[lk0*4+1][lrow] = pb0.y;
        Bs[lk0*4+2][lrow] = pb0.z;  Bs[lk0*4+3][lrow] = pb0.w;
        Bs[lk0*4+4][lrow] = pb1.x;  Bs[lk0*4+5][lrow] = pb1.y;
        Bs[lk0*4+6][lrow] = pb1.z;  Bs[lk0*4+7][lrow] = pb1.w;
        __syncthreads();

        if (kt < 127) {   // register prefetch of next k-slab, hidden under FMAs
            aptr += 16; bptr += 16;
            pa0 = *(const float4*)(aptr);
            pa1 = *(const float4*)(aptr + 4);
            pb0 = *(const float4*)(bptr);
            pb1 = *(const float4*)(bptr + 4);
        }

        #pragma unroll
        for (int kk = 0; kk < 16; kk++) {
            float a[8], b[8];
            *(float4*)&a[0] = *(const float4*)&As[kk][ty*8];
            *(float4*)&a[4] = *(const float4*)&As[kk][ty*8+4];
            *(float4*)&b[0] = *(const float4*)&Bs[kk][tx*8];
            *(float4*)&b[4] = *(const float4*)&Bs[kk][tx*8+4];
            #pragma unroll
            for (int i = 0; i < 8; i++)
                #pragma unroll
                for (int j = 0; j < 8; j++)
                    acc[i][j] += a[i] * b[j];
        }
    }

    // epilogue
    float bregs[8];
    #pragma unroll
    for (int j = 0; j < 8; j++) bregs[j] = bias[n0 + tx*8 + j];

    if (MODE == 0) {
        #pragma unroll
        for (int i = 0; i < 8; i++) {
            int m = m0 + ty*8 + i;
            float v[8];
            #pragma unroll
            for (int j = 0; j < 8; j++) v[j] = acc[i][j] + bregs[j];
            float* dst = outp + (size_t)m * 2048 + n0 + tx*8;
            *(float4*)(dst)     = *(float4*)&v[0];
            *(float4*)(dst + 4) = *(float4*)&v[4];
        }
    } else {
        float* qkv = (MODE == 2) ? g_Q : (MODE == 3) ? g_K : g_V;
        const int n    = n0 + tx*8;
        const int h    = n >> 7;
        const int dim0 = n & 127;         // 8-aligned -> all 8 cols in one head
        #pragma unroll
        for (int i = 0; i < 8; i++) {
            int m   = m0 + ty*8 + i;
            int bb  = m >> 11;
            int pos = m & 2047;
            float v[8];
            #pragma unroll
            for (int j = 0; j < 8; j++) v[j] = acc[i][j] + bregs[j];
            if (MODE == 2 || MODE == 3) {
                #pragma unroll
                for (int jp = 0; jp < 8; jp += 2) {
                    int p = (dim0 + jp) >> 1;
                    float cs = g_cos[pos*64 + p];
                    float sn = g_sin[pos*64 + p];
                    float x1 = v[jp], x2 = v[jp+1];
                    v[jp]   = x1*cs - x2*sn;
                    v[jp+1] = x1*sn + x2*cs;
                }
            }
            float* dst = qkv + (((size_t)(bb*NHEADS + h) * SEQLEN + pos) * DHEAD + dim0);
            *(float4*)(dst)     = *(float4*)&v[0];
            *(float4*)(dst + 4) = *(float4*)&v[4];
        }
    }
}

// ---------------- flash attention (fp32, causal, online softmax) ------------------
// grid: (32 q-tiles, 32 bh), 256 threads, BQ=BKV=64, d=128
#define SM_QS   0                       // 64*128
#define SM_KT   (64*128)                // 128*68 (transposed, padded)
#define SM_VS   (SM_KT + 128*68)        // 64*132
#define SM_SS   (SM_VS + 64*132)        // 64*68
#define SM_M    (SM_SS + 64*68)
#define SM_L    (SM_M + 64)
#define SM_F    (SM_L + 64)
#define SM_ATTN_BYTES ((SM_F + 64) * 4) // 119552 bytes

__global__ void __launch_bounds__(256, 1)
attn_kernel()
{
    extern __shared__ float sm[];
    float* Qs  = sm + SM_QS;
    float* Kt  = sm + SM_KT;
    float* Vs  = sm + SM_VS;
    float* Ss  = sm + SM_SS;
    float* m_s = sm + SM_M;
    float* l_s = sm + SM_L;
    float* f_s = sm + SM_F;

    const int tid = threadIdx.x;
    const int bh  = blockIdx.y;
    const int qt  = gridDim.x - 1 - blockIdx.x;   // heavy tiles first
    const int q0  = qt * 64;
    const float scale = 0.08838834764831845f;     // 1/sqrt(128)

    // load + scale Q tile
    const float* Qg = g_Q + ((size_t)bh * SEQLEN + q0) * DHEAD;
    for (int f = tid; f < 2048; f += 256) {       // 2048 float4
        int r  = f >> 5;
        int kq = (f & 31) << 2;
        float4 v = *(const float4*)(Qg + r*DHEAD + kq);
        v.x *= scale; v.y *= scale; v.z *= scale; v.w *= scale;
        *(float4*)&Qs[r*128 + kq] = v;
    }
    if (tid < 64) { m_s[tid] = -INFINITY; l_s[tid] = 0.f; }

    // mappings
    const int tx  = tid & 15, ty = tid >> 4;      // S-compute: 4x4 each
    const int rs0 = ty * 4,  cs0 = tx * 4;
    const int srow = tid >> 2, ssub = tid & 3;    // softmax: 4 threads/row
    const int rp  = tid >> 3, cg = tid & 7;       // PV: 2 rows x 16 cols
    const int r0o = rp * 2,  c0o = cg * 16;

    float o[2][16];
    #pragma unroll
    for (int c = 0; c < 16; c++) { o[0][c] = 0.f; o[1][c] = 0.f; }

    for (int jt = 0; jt <= qt; jt++) {
        const int kv0 = jt * 64;
        __syncthreads();   // previous tile fully consumed (also covers Q-load on iter 0)

        const float* Kg = g_K + ((size_t)bh * SEQLEN + kv0) * DHEAD;
        const float* Vg = g_V + ((size_t)bh * SEQLEN + kv0) * DHEAD;
        for (int f = tid; f < 2048; f += 256) {
            int j  = f >> 5;
            int kq = (f & 31) << 2;
            float4 kv = *(const float4*)(Kg + j*DHEAD + kq);
            Kt[(kq+0)*68 + j] = kv.x;
            Kt[(kq+1)*68 + j] = kv.y;
            Kt[(kq+2)*68 + j] = kv.z;
            Kt[(kq+3)*68 + j] = kv.w;
            *(float4*)&Vs[j*132 + kq] = *(const float4*)(Vg + j*DHEAD + kq);
        }
        __syncthreads();

        // ---- S = Q K^T ----
        float s[4][4];
        #pragma unroll
        for (int i = 0; i < 4; i++)
            #pragma unroll
            for (int j = 0; j < 4; j++) s[i][j] = 0.f;

        #pragma unroll 8
        for (int k = 0; k < 128; k++) {
            float a0 = Qs[(rs0+0)*128 + k];
            float a1 = Qs[(rs0+1)*128 + k];
            float a2 = Qs[(rs0+2)*128 + k];
            float a3 = Qs[(rs0+3)*128 + k];
            float4 bv = *(const float4*)&Kt[k*68 + cs0];
            s[0][0] += a0*bv.x; s[0][1] += a0*bv.y; s[0][2] += a0*bv.z; s[0][3] += a0*bv.w;
            s[1][0] += a1*bv.x; s[1][1] += a1*bv.y; s[1][2] += a1*bv.z; s[1][3] += a1*bv.w;
            s[2][0] += a2*bv.x; s[2][1] += a2*bv.y; s[2][2] += a2*bv.z; s[2][3] += a2*bv.w;
            s[3][0] += a3*bv.x; s[3][1] += a3*bv.y; s[3][2] += a3*bv.z; s[3][3] += a3*bv.w;
        }
        #pragma unroll
        for (int i = 0; i < 4; i++)
            #pragma unroll
            for (int j = 0; j < 4; j++)
                Ss[(rs0+i)*68 + cs0 + j] = s[i][j];
        __syncthreads();

        // ---- online softmax update ----
        const bool diag = (jt == qt);
        float pv[16];
        float mx = -INFINITY;
        #pragma unroll
        for (int t = 0; t < 16; t++) {
            int c = ssub*16 + t;
            float v = Ss[srow*68 + c];
            if (diag && c > srow) v = -1e30f;
            pv[t] = v;
            mx = fmaxf(mx, v);
        }
        mx = fmaxf(mx, __shfl_xor_sync(0xffffffffu, mx, 1));
        mx = fmaxf(mx, __shfl_xor_sync(0xffffffffu, mx, 2));
        float m_old = m_s[srow];
        float m_new = fmaxf(m_old, mx);
        float sum = 0.f;
        #pragma unroll
        for (int t = 0; t < 16; t++) {
            float p = __expf(pv[t] - m_new);
            Ss[srow*68 + ssub*16 + t] = p;
            sum += p;
        }
        sum += __shfl_xor_sync(0xffffffffu, sum, 1);
        sum += __shfl_xor_sync(0xffffffffu, sum, 2);
        if (ssub == 0) {
            float fac = __expf(m_old - m_new);
            f_s[srow] = fac;
            m_s[srow] = m_new;
            l_s[srow] = l_s[srow] * fac + sum;
        }
        __syncthreads();

        // ---- O = O*fac + P V ----
        float f0 = f_s[r0o], f1 = f_s[r0o + 1];
        #pragma unroll
        for (int c = 0; c < 16; c++) { o[0][c] *= f0; o[1][c] *= f1; }

        #pragma unroll 4
        for (int j = 0; j < 64; j++) {
            float p0 = Ss[(r0o  )*68 + j];
            float p1 = Ss[(r0o+1)*68 + j];
            #pragma unroll
            for (int cc = 0; cc < 4; cc++) {
                float4 v = *(const float4*)&Vs[j*132 + c0o + cc*4];
                o[0][cc*4+0] += p0*v.x; o[0][cc*4+1] += p0*v.y;
                o[0][cc*4+2] += p0*v.z; o[0][cc*4+3] += p0*v.w;
                o[1][cc*4+0] += p1*v.x; o[1][cc*4+1] += p1*v.y;
                o[1][cc*4+2] += p1*v.z; o[1][cc*4+3] += p1*v.w;
            }
        }
    }

    // ---- normalize + store into [b][s][d_model] ----
    float inv0 = 1.f / l_s[r0o];
    float inv1 = 1.f / l_s[r0o + 1];
    int bb = bh >> 4, h = bh & 15;
    float* out0 = g_A + ((size_t)(bb*SEQLEN + q0 + r0o)) * D_MODEL + h*DHEAD + c0o;
    float* out1 = out0 + D_MODEL;
    float v0[16], v1[16];
    #pragma unroll
    for (int c = 0; c < 16; c++) { v0[c] = o[0][c]*inv0; v1[c] = o[1][c]*inv1; }
    #pragma unroll
    for (int cc = 0; cc < 4; cc++) {
        *(float4*)(out0 + cc*4) = *(float4*)&v0[cc*4];
        *(float4*)(out1 + cc*4) = *(float4*)&v1[cc*4];
    }
}

// ---------------- launch -----------------------------------------------------------
extern "C" void kernel_launch(void* const* d_in, const int* in_sizes, int n_in,
                              void* d_out, int out_size)
{
    const float* x  = (const float*)d_in[0];
    const float* Wq = (const float*)d_in[1];
    const float* bq = (const float*)d_in[2];
    const float* Wk = (const float*)d_in[3];
    const float* bk = (const float*)d_in[4];
    const float* Wv = (const float*)d_in[5];
    const float* bv = (const float*)d_in[6];
    const float* Wo = (const float*)d_in[7];
    const float* bo = (const float*)d_in[8];
    float* out = (float*)d_out;

    cudaFuncSetAttribute(attn_kernel, cudaFuncAttributeMaxDynamicSharedMemorySize,
                         SM_ATTN_BYTES);

    rope_table_kernel<<<512, 256>>>();

    dim3 gg(16, 32);
    gemm_kernel<2><<<gg, 256>>>(x, Wq, bq, nullptr);   // Q + RoPE
    gemm_kernel<3><<<gg, 256>>>(x, Wk, bk, nullptr);   // K + RoPE
    gemm_kernel<1><<<gg, 256>>>(x, Wv, bv, nullptr);   // V

    attn_kernel<<<dim3(32, 32), 256, SM_ATTN_BYTES>>>();

    gemm_kernel<0><<<gg, 256>>>(x /*ignored: reads g_A*/, Wo, bo, out);
}

// round 5
// speedup vs baseline: 1.2210x; 1.2210x over previous
#include <cuda_runtime.h>
#include <cuda_bf16.h>
#include <math.h>
#include <stdint.h>

#define D_MODEL 2048
#define NHEADS  16
#define DHEAD   128
#define SEQLEN  2048
#define BATCH   2
#define MROWS   (BATCH*SEQLEN)   // 4096

// ---------------- scratch (device globals; no allocation allowed) ----------------
__device__ float g_Q[BATCH*NHEADS*SEQLEN*DHEAD];   // [bh][s][128]
__device__ float g_K[BATCH*NHEADS*SEQLEN*DHEAD];
__device__ float g_V[BATCH*NHEADS*SEQLEN*DHEAD];
__device__ float g_A[BATCH*SEQLEN*D_MODEL];        // attn out, [b][s][d_model]
__device__ float g_cos[SEQLEN*(DHEAD/2)];
__device__ float g_sin[SEQLEN*(DHEAD/2)];

// bf16 hi/lo splits (3-term split GEMM: hi*hi + hi*lo + lo*hi)
__device__ __nv_bfloat16 g_xhi[MROWS*D_MODEL];
__device__ __nv_bfloat16 g_xlo[MROWS*D_MODEL];
__device__ __nv_bfloat16 g_whi[4][D_MODEL*D_MODEL];   // 0=Wq 1=Wk 2=Wv 3=Wo
__device__ __nv_bfloat16 g_wlo[4][D_MODEL*D_MODEL];
__device__ __nv_bfloat16 g_ahi[MROWS*D_MODEL];
__device__ __nv_bfloat16 g_alo[MROWS*D_MODEL];

// ---------------- PTX helpers (sm_80-level only: no 'a' features) ------------------
__device__ __forceinline__ uint32_t smem_u32(const void* p) {
    uint32_t a;
    asm("{ .reg .u64 t; cvta.to.shared.u64 t, %1; cvt.u32.u64 %0, t; }" : "=r"(a) : "l"(p));
    return a;
}
__device__ __forceinline__ void cp16(uint32_t dst, const void* src) {
    asm volatile("cp.async.cg.shared.global [%0], [%1], 16;" :: "r"(dst), "l"(src));
}
#define CP_COMMIT() asm volatile("cp.async.commit_group;" ::: "memory")
#define CP_WAIT(n)  asm volatile("cp.async.wait_group %0;" :: "n"(n) : "memory")

__device__ __forceinline__ void ldm_x4(uint32_t* r, uint32_t addr) {
    asm volatile("ldmatrix.sync.aligned.m8n8.x4.shared.b16 {%0,%1,%2,%3}, [%4];"
                 : "=r"(r[0]), "=r"(r[1]), "=r"(r[2]), "=r"(r[3]) : "r"(addr));
}
__device__ __forceinline__ void mma_bf16(float* c, const uint32_t* a, uint32_t b0, uint32_t b1) {
    asm volatile("mma.sync.aligned.m16n8k16.row.col.f32.bf16.bf16.f32 "
                 "{%0,%1,%2,%3}, {%4,%5,%6,%7}, {%8,%9}, {%0,%1,%2,%3};"
                 : "+f"(c[0]), "+f"(c[1]), "+f"(c[2]), "+f"(c[3])
                 : "r"(a[0]), "r"(a[1]), "r"(a[2]), "r"(a[3]), "r"(b0), "r"(b1));
}

// ---------------- RoPE tables (double precision) -----------------------------------
__global__ void rope_table_kernel() {
    int idx = blockIdx.x * blockDim.x + threadIdx.x;   // 2048*64 threads
    int pos = idx >> 6;
    int p   = idx & 63;
    double freq = exp(-((double)(2 * p) / 128.0) * log(10000.0));
    double ang  = (double)pos * freq;
    g_cos[idx] = (float)cos(ang);
    g_sin[idx] = (float)sin(ang);
}

// ---------------- hi/lo bf16 split kernels -----------------------------------------
// WHICH: 0=x, 1..4=W[0..3], 5=g_A (src ignored)
template<int WHICH>
__global__ void split_kernel(const float* __restrict__ src, int n) {
    int i = blockIdx.x * 256 + threadIdx.x;
    if (i >= n) return;
    const float* s = (WHICH == 5) ? (const float*)g_A : src;
    __nv_bfloat16 *hi, *lo;
    if      (WHICH == 0) { hi = g_xhi; lo = g_xlo; }
    else if (WHICH == 5) { hi = g_ahi; lo = g_alo; }
    else                 { hi = g_whi[WHICH-1]; lo = g_wlo[WHICH-1]; }
    float v = s[i];
    __nv_bfloat16 h = __float2bfloat16(v);
    hi[i] = h;
    lo[i] = __float2bfloat16(v - __bfloat162float(h));
}

// ---------------- mma.sync split-bf16 GEMM -----------------------------------------
// C[M=4096, N=2048] = A[M,K=2048] * W[N,K]^T + bias  via hi*hi + hi*lo + lo*hi
// MODE: 0 = out (reads g_ahi/lo), 1 = V, 2 = Q(+RoPE), 3 = K(+RoPE)
// BM=BN=128, BK=32, 256 threads (8 warps, 4m x 2n), warp tile 32x64.
#define GLD 40                                // padded halves per row (conflict-free ldmatrix)
#define T_A_HI 0
#define T_A_LO (128*GLD)
#define T_B_HI (2*128*GLD)
#define T_B_LO (3*128*GLD)
#define STAGE_HALVES (4*128*GLD)              // 20480 halves = 40960 B
#define SMEM_GEMM_BYTES (2*STAGE_HALVES*2)    // 81920 B

template<int MODE>
__global__ void __launch_bounds__(256, 1)
gemm_mma(const float* __restrict__ bias, float* __restrict__ outp)
{
    extern __shared__ __nv_bfloat16 smem[];
    const uint32_t sb = smem_u32(smem);
    const int tid  = threadIdx.x;
    const int lane = tid & 31, warp = tid >> 5;
    const int wm   = warp & 3, wn = warp >> 2;
    const int m0   = blockIdx.y * 128;
    const int n0   = blockIdx.x * 128;

    constexpr int WIDX = (MODE == 2) ? 0 : (MODE == 3) ? 1 : (MODE == 1) ? 2 : 3;
    const __nv_bfloat16* Ahi = (MODE == 0) ? g_ahi : g_xhi;
    const __nv_bfloat16* Alo = (MODE == 0) ? g_alo : g_xlo;
    const __nv_bfloat16* Bhi = g_whi[WIDX];
    const __nv_bfloat16* Blo = g_wlo[WIDX];

    // loader mapping: row = tid&127, chunks {lc, lc+2} (16B each)
    const int lrow = tid & 127;
    const int lc   = tid >> 7;               // 0 or 1
    const __nv_bfloat16* pAh = Ahi + (size_t)(m0 + lrow) * 2048;
    const __nv_bfloat16* pAl = Alo + (size_t)(m0 + lrow) * 2048;
    const __nv_bfloat16* pBh = Bhi + (size_t)(n0 + lrow) * 2048;
    const __nv_bfloat16* pBl = Blo + (size_t)(n0 + lrow) * 2048;

    auto load_stage = [&](int s, int buf) {
        const int k0 = s * 32;
        const uint32_t base = sb + buf * STAGE_HALVES * 2;
        #pragma unroll
        for (int q = 0; q < 2; q++) {
            const int c = lc + q * 2;                       // chunk 0..3
            const uint32_t off = (lrow * GLD + c * 8) * 2;  // bytes
            const int ks = k0 + c * 8;
            cp16(base + T_A_HI*2 + off, pAh + ks);
            cp16(base + T_A_LO*2 + off, pAl + ks);
            cp16(base + T_B_HI*2 + off, pBh + ks);
            cp16(base + T_B_LO*2 + off, pBl + ks);
        }
    };

    float acc[2][8][4];
    #pragma unroll
    for (int i = 0; i < 2; i++)
        #pragma unroll
        for (int j = 0; j < 8; j++)
            #pragma unroll
            for (int k = 0; k < 4; k++) acc[i][j][k] = 0.f;

    // ldmatrix per-lane source rows
    const int lr = lane & 15;        // row within 16-row group
    const int lh = lane >> 4;        // k-half (0/1 -> +8 halves)

    load_stage(0, 0); CP_COMMIT();

    for (int s = 0; s < 64; s++) {
        if (s + 1 < 64) { load_stage(s + 1, (s + 1) & 1); CP_COMMIT(); CP_WAIT(1); }
        else            { CP_WAIT(0); }
        __syncthreads();

        const uint32_t base = sb + (s & 1) * STAGE_HALVES * 2;
        #pragma unroll
        for (int kk = 0; kk < 32; kk += 16) {
            uint32_t ah[2][4], al[2][4], bh[4][4], bl[4][4];
            #pragma unroll
            for (int mf = 0; mf < 2; mf++) {
                uint32_t ra = base + ((wm*32 + mf*16 + lr) * GLD + kk + lh*8) * 2;
                ldm_x4(ah[mf], ra + T_A_HI*2);
                ldm_x4(al[mf], ra + T_A_LO*2);
            }
            #pragma unroll
            for (int nb = 0; nb < 4; nb++) {
                uint32_t rb = base + ((wn*64 + nb*16 + lr) * GLD + kk + lh*8) * 2;
                ldm_x4(bh[nb], rb + T_B_HI*2);
                ldm_x4(bl[nb], rb + T_B_LO*2);
            }
            // B fragment pairing: x4 returns (n0-7,k0-7),(n8-15,k0-7),(n0-7,k8-15),(n8-15,k8-15)
            // mma wants b0=k0-7, b1=k8-15 for SAME n-group -> pairs (sub, sub+2)
            #pragma unroll
            for (int mf = 0; mf < 2; mf++)
                #pragma unroll
                for (int nb = 0; nb < 4; nb++)
                    #pragma unroll
                    for (int sub = 0; sub < 2; sub++) {
                        float* c = acc[mf][nb*2 + sub];
                        mma_bf16(c, ah[mf], bh[nb][sub], bh[nb][sub+2]);
                        mma_bf16(c, ah[mf], bl[nb][sub], bl[nb][sub+2]);
                        mma_bf16(c, al[mf], bh[nb][sub], bh[nb][sub+2]);
                    }
        }
        __syncthreads();
    }

    // ---- epilogue: bias (+RoPE) + layout ----
    const int g = lane >> 2, t = lane & 3;
    #pragma unroll
    for (int mf = 0; mf < 2; mf++) {
        const int r0 = m0 + wm*32 + mf*16 + g;   // and r0+8
        const int r1 = r0 + 8;
        const int bb0 = r0 >> 11, pos0 = r0 & 2047;
        const int bb1 = r1 >> 11, pos1 = r1 & 2047;
        #pragma unroll
        for (int nf = 0; nf < 8; nf++) {
            const int col = n0 + wn*64 + nf*8 + 2*t;   // even
            float b0 = bias[col], b1 = bias[col + 1];
            float v00 = acc[mf][nf][0] + b0, v01 = acc[mf][nf][1] + b1;
            float v10 = acc[mf][nf][2] + b0, v11 = acc[mf][nf][3] + b1;
            if (MODE == 2 || MODE == 3) {
                const int p = (col & 127) >> 1;        // RoPE pair index WITHIN head
                float cs0 = g_cos[pos0*64 + p], sn0 = g_sin[pos0*64 + p];
                float cs1 = g_cos[pos1*64 + p], sn1 = g_sin[pos1*64 + p];
                float x1 = v00, x2 = v01;
                v00 = x1*cs0 - x2*sn0;  v01 = x1*sn0 + x2*cs0;
                x1 = v10; x2 = v11;
                v10 = x1*cs1 - x2*sn1;  v11 = x1*sn1 + x2*cs1;
            }
            if (MODE == 0) {
                float2* d0 = (float2*)(outp + (size_t)r0 * 2048 + col);
                float2* d1 = (float2*)(outp + (size_t)r1 * 2048 + col);
                *d0 = make_float2(v00, v01);
                *d1 = make_float2(v10, v11);
            } else {
                float* qkv = (MODE == 2) ? g_Q : (MODE == 3) ? g_K : g_V;
                const int h = col >> 7, d = col & 127;
                float2* d0 = (float2*)(qkv + (((size_t)(bb0*NHEADS + h) * SEQLEN + pos0) * DHEAD + d));
                float2* d1 = (float2*)(qkv + (((size_t)(bb1*NHEADS + h) * SEQLEN + pos1) * DHEAD + d));
                *d0 = make_float2(v00, v01);
                *d1 = make_float2(v10, v11);
            }
        }
    }
}

// ---------------- flash attention (fp32, causal, online softmax) ------------------
// grid: (32 q-tiles, 32 bh), 256 threads, BQ=BKV=64, d=128
#define SM_QS   0                       // 64*128
#define SM_KT   (64*128)                // 128*68 (transposed, padded)
#define SM_VS   (SM_KT + 128*68)        // 64*132
#define SM_SS   (SM_VS + 64*132)        // 64*68
#define SM_M    (SM_SS + 64*68)
#define SM_L    (SM_M + 64)
#define SM_F    (SM_L + 64)
#define SM_ATTN_BYTES ((SM_F + 64) * 4) // 119552 bytes

__global__ void __launch_bounds__(256, 1)
attn_kernel()
{
    extern __shared__ float sm[];
    float* Qs  = sm + SM_QS;
    float* Kt  = sm + SM_KT;
    float* Vs  = sm + SM_VS;
    float* Ss  = sm + SM_SS;
    float* m_s = sm + SM_M;
    float* l_s = sm + SM_L;
    float* f_s = sm + SM_F;

    const int tid = threadIdx.x;
    const int bh  = blockIdx.y;
    const int qt  = gridDim.x - 1 - blockIdx.x;   // heavy tiles first
    const int q0  = qt * 64;
    const float scale = 0.08838834764831845f;     // 1/sqrt(128)

    const float* Qg = g_Q + ((size_t)bh * SEQLEN + q0) * DHEAD;
    for (int f = tid; f < 2048; f += 256) {
        int r  = f >> 5;
        int kq = (f & 31) << 2;
        float4 v = *(const float4*)(Qg + r*DHEAD + kq);
        v.x *= scale; v.y *= scale; v.z *= scale; v.w *= scale;
        *(float4*)&Qs[r*128 + kq] = v;
    }
    if (tid < 64) { m_s[tid] = -INFINITY; l_s[tid] = 0.f; }

    const int tx  = tid & 15, ty = tid >> 4;
    const int rs0 = ty * 4,  cs0 = tx * 4;
    const int srow = tid >> 2, ssub = tid & 3;
    const int rp  = tid >> 3, cg = tid & 7;
    const int r0o = rp * 2,  c0o = cg * 16;

    float o[2][16];
    #pragma unroll
    for (int c = 0; c < 16; c++) { o[0][c] = 0.f; o[1][c] = 0.f; }

    for (int jt = 0; jt <= qt; jt++) {
        const int kv0 = jt * 64;
        __syncthreads();

        const float* Kg = g_K + ((size_t)bh * SEQLEN + kv0) * DHEAD;
        const float* Vg = g_V + ((size_t)bh * SEQLEN + kv0) * DHEAD;
        for (int f = tid; f < 2048; f += 256) {
            int j  = f >> 5;
            int kq = (f & 31) << 2;
            float4 kv = *(const float4*)(Kg + j*DHEAD + kq);
            Kt[(kq+0)*68 + j] = kv.x;
            Kt[(kq+1)*68 + j] = kv.y;
            Kt[(kq+2)*68 + j] = kv.z;
            Kt[(kq+3)*68 + j] = kv.w;
            *(float4*)&Vs[j*132 + kq] = *(const float4*)(Vg + j*DHEAD + kq);
        }
        __syncthreads();

        float s[4][4];
        #pragma unroll
        for (int i = 0; i < 4; i++)
            #pragma unroll
            for (int j = 0; j < 4; j++) s[i][j] = 0.f;

        #pragma unroll 8
        for (int k = 0; k < 128; k++) {
            float a0 = Qs[(rs0+0)*128 + k];
            float a1 = Qs[(rs0+1)*128 + k];
            float a2 = Qs[(rs0+2)*128 + k];
            float a3 = Qs[(rs0+3)*128 + k];
            float4 bv = *(const float4*)&Kt[k*68 + cs0];
            s[0][0] += a0*bv.x; s[0][1] += a0*bv.y; s[0][2] += a0*bv.z; s[0][3] += a0*bv.w;
            s[1][0] += a1*bv.x; s[1][1] += a1*bv.y; s[1][2] += a1*bv.z; s[1][3] += a1*bv.w;
            s[2][0] += a2*bv.x; s[2][1] += a2*bv.y; s[2][2] += a2*bv.z; s[2][3] += a2*bv.w;
            s[3][0] += a3*bv.x; s[3][1] += a3*bv.y; s[3][2] += a3*bv.z; s[3][3] += a3*bv.w;
        }
        #pragma unroll
        for (int i = 0; i < 4; i++)
            #pragma unroll
            for (int j = 0; j < 4; j++)
                Ss[(rs0+i)*68 + cs0 + j] = s[i][j];
        __syncthreads();

        const bool diag = (jt == qt);
        float pv[16];
        float mx = -INFINITY;
        #pragma unroll
        for (int t = 0; t < 16; t++) {
            int c = ssub*16 + t;
            float v = Ss[srow*68 + c];
            if (diag && c > srow) v = -1e30f;
            pv[t] = v;
            mx = fmaxf(mx, v);
        }
        mx = fmaxf(mx, __shfl_xor_sync(0xffffffffu, mx, 1));
        mx = fmaxf(mx, __shfl_xor_sync(0xffffffffu, mx, 2));
        float m_old = m_s[srow];
        float m_new = fmaxf(m_old, mx);
        float sum = 0.f;
        #pragma unroll
        for (int t = 0; t < 16; t++) {
            float p = __expf(pv[t] - m_new);
            Ss[srow*68 + ssub*16 + t] = p;
            sum += p;
        }
        sum += __shfl_xor_sync(0xffffffffu, sum, 1);
        sum += __shfl_xor_sync(0xffffffffu, sum, 2);
        if (ssub == 0) {
            float fac = __expf(m_old - m_new);
            f_s[srow] = fac;
            m_s[srow] = m_new;
            l_s[srow] = l_s[srow] * fac + sum;
        }
        __syncthreads();

        float f0 = f_s[r0o], f1 = f_s[r0o + 1];
        #pragma unroll
        for (int c = 0; c < 16; c++) { o[0][c] *= f0; o[1][c] *= f1; }

        #pragma unroll 4
        for (int j = 0; j < 64; j++) {
            float p0 = Ss[(r0o  )*68 + j];
            float p1 = Ss[(r0o+1)*68 + j];
            #pragma unroll
            for (int cc = 0; cc < 4; cc++) {
                float4 v = *(const float4*)&Vs[j*132 + c0o + cc*4];
                o[0][cc*4+0] += p0*v.x; o[0][cc*4+1] += p0*v.y;
                o[0][cc*4+2] += p0*v.z; o[0][cc*4+3] += p0*v.w;
                o[1][cc*4+0] += p1*v.x; o[1][cc*4+1] += p1*v.y;
                o[1][cc*4+2] += p1*v.z; o[1][cc*4+3] += p1*v.w;
            }
        }
    }

    float inv0 = 1.f / l_s[r0o];
    float inv1 = 1.f / l_s[r0o + 1];
    int bb = bh >> 4, h = bh & 15;
    float* out0 = g_A + ((size_t)(bb*SEQLEN + q0 + r0o)) * D_MODEL + h*DHEAD + c0o;
    float* out1 = out0 + D_MODEL;
    float v0[16], v1[16];
    #pragma unroll
    for (int c = 0; c < 16; c++) { v0[c] = o[0][c]*inv0; v1[c] = o[1][c]*inv1; }
    #pragma unroll
    for (int cc = 0; cc < 4; cc++) {
        *(float4*)(out0 + cc*4) = *(float4*)&v0[cc*4];
        *(float4*)(out1 + cc*4) = *(float4*)&v1[cc*4];
    }
}

// ---------------- launch -----------------------------------------------------------
extern "C" void kernel_launch(void* const* d_in, const int* in_sizes, int n_in,
                              void* d_out, int out_size)
{
    const float* x  = (const float*)d_in[0];
    const float* Wq = (const float*)d_in[1];
    const float* bq = (const float*)d_in[2];
    const float* Wk = (const float*)d_in[3];
    const float* bk = (const float*)d_in[4];
    const float* Wv = (const float*)d_in[5];
    const float* bv = (const float*)d_in[6];
    const float* Wo = (const float*)d_in[7];
    const float* bo = (const float*)d_in[8];
    float* out = (float*)d_out;

    cudaFuncSetAttribute(attn_kernel, cudaFuncAttributeMaxDynamicSharedMemorySize, SM_ATTN_BYTES);
    cudaFuncSetAttribute(gemm_mma<0>, cudaFuncAttributeMaxDynamicSharedMemorySize, SMEM_GEMM_BYTES);
    cudaFuncSetAttribute(gemm_mma<1>, cudaFuncAttributeMaxDynamicSharedMemorySize, SMEM_GEMM_BYTES);
    cudaFuncSetAttribute(gemm_mma<2>, cudaFuncAttributeMaxDynamicSharedMemorySize, SMEM_GEMM_BYTES);
    cudaFuncSetAttribute(gemm_mma<3>, cudaFuncAttributeMaxDynamicSharedMemorySize, SMEM_GEMM_BYTES);

    rope_table_kernel<<<512, 256>>>();

    const int NX = MROWS * D_MODEL;      // 8388608
    const int NW = D_MODEL * D_MODEL;    // 4194304
    split_kernel<0><<<NX/256, 256>>>(x,  NX);
    split_kernel<1><<<NW/256, 256>>>(Wq, NW);
    split_kernel<2><<<NW/256, 256>>>(Wk, NW);
    split_kernel<3><<<NW/256, 256>>>(Wv, NW);
    split_kernel<4><<<NW/256, 256>>>(Wo, NW);

    dim3 gg(16, 32);   // (N/128, M/128)
    gemm_mma<2><<<gg, 256, SMEM_GEMM_BYTES>>>(bq, nullptr);  // Q + RoPE
    gemm_mma<3><<<gg, 256, SMEM_GEMM_BYTES>>>(bk, nullptr);  // K + RoPE
    gemm_mma<1><<<gg, 256, SMEM_GEMM_BYTES>>>(bv, nullptr);  // V

    attn_kernel<<<dim3(32, 32), 256, SM_ATTN_BYTES>>>();

    split_kernel<5><<<NX/256, 256>>>(nullptr, NX);           // g_A -> hi/lo
    gemm_mma<0><<<gg, 256, SMEM_GEMM_BYTES>>>(bo, out);      // output projection
}

// round 6
// speedup vs baseline: 2.4322x; 1.9919x over previous
#include <cuda_runtime.h>
#include <cuda_bf16.h>
#include <math.h>
#include <stdint.h>

#define D_MODEL 2048
#define NHEADS  16
#define DHEAD   128
#define SEQLEN  2048
#define BATCH   2
#define MROWS   (BATCH*SEQLEN)   // 4096
#define QK_SCALE 0.08838834764831845f   // 1/sqrt(128)

// ---------------- scratch (device globals; no allocation allowed) ----------------
__device__ float g_cos[SEQLEN*(DHEAD/2)];
__device__ float g_sin[SEQLEN*(DHEAD/2)];

// bf16 hi/lo splits (3-term split GEMM: hi*hi + hi*lo + lo*hi)
__device__ __nv_bfloat16 g_xhi[MROWS*D_MODEL];
__device__ __nv_bfloat16 g_xlo[MROWS*D_MODEL];
__device__ __nv_bfloat16 g_whi[4][D_MODEL*D_MODEL];   // 0=Wq 1=Wk 2=Wv 3=Wo
__device__ __nv_bfloat16 g_wlo[4][D_MODEL*D_MODEL];
__device__ __nv_bfloat16 g_ahi[MROWS*D_MODEL];        // attention out, x-layout
__device__ __nv_bfloat16 g_alo[MROWS*D_MODEL];
// Q (scaled+RoPE), K (RoPE), V — bf16 hi/lo, [bh][s][128]
__device__ __nv_bfloat16 g_qhi[BATCH*NHEADS*SEQLEN*DHEAD];
__device__ __nv_bfloat16 g_qlo[BATCH*NHEADS*SEQLEN*DHEAD];
__device__ __nv_bfloat16 g_khi[BATCH*NHEADS*SEQLEN*DHEAD];
__device__ __nv_bfloat16 g_klo[BATCH*NHEADS*SEQLEN*DHEAD];
__device__ __nv_bfloat16 g_vhi[BATCH*NHEADS*SEQLEN*DHEAD];
__device__ __nv_bfloat16 g_vlo[BATCH*NHEADS*SEQLEN*DHEAD];

// ---------------- PTX helpers (sm_80-level only) -----------------------------------
__device__ __forceinline__ uint32_t smem_u32(const void* p) {
    uint32_t a;
    asm("{ .reg .u64 t; cvta.to.shared.u64 t, %1; cvt.u32.u64 %0, t; }" : "=r"(a) : "l"(p));
    return a;
}
__device__ __forceinline__ void cp16(uint32_t dst, const void* src) {
    asm volatile("cp.async.cg.shared.global [%0], [%1], 16;" :: "r"(dst), "l"(src));
}
#define CP_COMMIT() asm volatile("cp.async.commit_group;" ::: "memory")
#define CP_WAIT(n)  asm volatile("cp.async.wait_group %0;" :: "n"(n) : "memory")

__device__ __forceinline__ void ldm_x4(uint32_t* r, uint32_t addr) {
    asm volatile("ldmatrix.sync.aligned.m8n8.x4.shared.b16 {%0,%1,%2,%3}, [%4];"
                 : "=r"(r[0]), "=r"(r[1]), "=r"(r[2]), "=r"(r[3]) : "r"(addr));
}
__device__ __forceinline__ void ldm_x4_t(uint32_t* r, uint32_t addr) {
    asm volatile("ldmatrix.sync.aligned.m8n8.x4.trans.shared.b16 {%0,%1,%2,%3}, [%4];"
                 : "=r"(r[0]), "=r"(r[1]), "=r"(r[2]), "=r"(r[3]) : "r"(addr));
}
__device__ __forceinline__ void mma_bf16(float* c, const uint32_t* a, uint32_t b0, uint32_t b1) {
    asm volatile("mma.sync.aligned.m16n8k16.row.col.f32.bf16.bf16.f32 "
                 "{%0,%1,%2,%3}, {%4,%5,%6,%7}, {%8,%9}, {%0,%1,%2,%3};"
                 : "+f"(c[0]), "+f"(c[1]), "+f"(c[2]), "+f"(c[3])
                 : "r"(a[0]), "r"(a[1]), "r"(a[2]), "r"(a[3]), "r"(b0), "r"(b1));
}
__device__ __forceinline__ uint32_t packbf2(float lo, float hi) {
    uint32_t r;
    asm("cvt.rn.bf16x2.f32 %0, %1, %2;" : "=r"(r) : "f"(hi), "f"(lo));  // first src -> upper
    return r;
}

// ---------------- RoPE tables (double precision) -----------------------------------
__global__ void rope_table_kernel() {
    int idx = blockIdx.x * blockDim.x + threadIdx.x;
    int pos = idx >> 6;
    int p   = idx & 63;
    double freq = exp(-((double)(2 * p) / 128.0) * log(10000.0));
    double ang  = (double)pos * freq;
    g_cos[idx] = (float)cos(ang);
    g_sin[idx] = (float)sin(ang);
}

// ---------------- hi/lo bf16 split kernels (inputs only) ---------------------------
// WHICH: 0=x, 1..4=W[0..3]
template<int WHICH>
__global__ void split_kernel(const float* __restrict__ src, int n) {
    int i = blockIdx.x * 256 + threadIdx.x;
    if (i >= n) return;
    __nv_bfloat16 *hi, *lo;
    if (WHICH == 0) { hi = g_xhi; lo = g_xlo; }
    else            { hi = g_whi[WHICH-1]; lo = g_wlo[WHICH-1]; }
    float v = src[i];
    __nv_bfloat16 h = __float2bfloat16(v);
    hi[i] = h;
    lo[i] = __float2bfloat16(v - __bfloat162float(h));
}

// ---------------- mma.sync split-bf16 GEMM -----------------------------------------
// MODE: 0 = out (reads g_ahi/lo, writes fp32 outp), 1 = V, 2 = Q(+RoPE+scale), 3 = K(+RoPE)
// BM=BN=128, BK=32, 256 threads (8 warps, 4m x 2n), warp tile 32x64, 3-stage pipe.
#define GLD 40
#define T_A_HI 0
#define T_A_LO (128*GLD)
#define T_B_HI (2*128*GLD)
#define T_B_LO (3*128*GLD)
#define STAGE_HALVES (4*128*GLD)              // 20480 halves = 40960 B
#define SMEM_GEMM_BYTES (3*STAGE_HALVES*2)    // 122880 B

template<int MODE>
__global__ void __launch_bounds__(256, 1)
gemm_mma(const float* __restrict__ bias, float* __restrict__ outp)
{
    extern __shared__ __nv_bfloat16 smem[];
    const uint32_t sb = smem_u32(smem);
    const int tid  = threadIdx.x;
    const int lane = tid & 31, warp = tid >> 5;
    const int wm   = warp & 3, wn = warp >> 2;
    const int m0   = blockIdx.y * 128;
    const int n0   = blockIdx.x * 128;

    constexpr int WIDX = (MODE == 2) ? 0 : (MODE == 3) ? 1 : (MODE == 1) ? 2 : 3;
    const __nv_bfloat16* Ahi = (MODE == 0) ? g_ahi : g_xhi;
    const __nv_bfloat16* Alo = (MODE == 0) ? g_alo : g_xlo;
    const __nv_bfloat16* Bhi = g_whi[WIDX];
    const __nv_bfloat16* Blo = g_wlo[WIDX];

    const int lrow = tid & 127;
    const int lc   = tid >> 7;
    const __nv_bfloat16* pAh = Ahi + (size_t)(m0 + lrow) * 2048;
    const __nv_bfloat16* pAl = Alo + (size_t)(m0 + lrow) * 2048;
    const __nv_bfloat16* pBh = Bhi + (size_t)(n0 + lrow) * 2048;
    const __nv_bfloat16* pBl = Blo + (size_t)(n0 + lrow) * 2048;

    auto load_stage = [&](int s, int buf) {
        const int k0 = s * 32;
        const uint32_t base = sb + buf * STAGE_HALVES * 2;
        #pragma unroll
        for (int q = 0; q < 2; q++) {
            const int c = lc + q * 2;
            const uint32_t off = (lrow * GLD + c * 8) * 2;
            const int ks = k0 + c * 8;
            cp16(base + T_A_HI*2 + off, pAh + ks);
            cp16(base + T_A_LO*2 + off, pAl + ks);
            cp16(base + T_B_HI*2 + off, pBh + ks);
            cp16(base + T_B_LO*2 + off, pBl + ks);
        }
    };

    float acc[2][8][4];
    #pragma unroll
    for (int i = 0; i < 2; i++)
        #pragma unroll
        for (int j = 0; j < 8; j++)
            #pragma unroll
            for (int k = 0; k < 4; k++) acc[i][j][k] = 0.f;

    const int lr = lane & 15;
    const int lh = lane >> 4;

    load_stage(0, 0); CP_COMMIT();
    load_stage(1, 1); CP_COMMIT();

    for (int s = 0; s < 64; s++) {
        if (s + 2 < 64) { load_stage(s + 2, (s + 2) % 3); CP_COMMIT(); }
        if      (s < 62)  CP_WAIT(2);
        else if (s == 62) CP_WAIT(1);
        else              CP_WAIT(0);
        __syncthreads();

        const uint32_t base = sb + (s % 3) * STAGE_HALVES * 2;
        #pragma unroll
        for (int kk = 0; kk < 32; kk += 16) {
            uint32_t ah[2][4], al[2][4], bh[4][4], bl[4][4];
            #pragma unroll
            for (int mf = 0; mf < 2; mf++) {
                uint32_t ra = base + ((wm*32 + mf*16 + lr) * GLD + kk + lh*8) * 2;
                ldm_x4(ah[mf], ra + T_A_HI*2);
                ldm_x4(al[mf], ra + T_A_LO*2);
            }
            #pragma unroll
            for (int nb = 0; nb < 4; nb++) {
                uint32_t rb = base + ((wn*64 + nb*16 + lr) * GLD + kk + lh*8) * 2;
                ldm_x4(bh[nb], rb + T_B_HI*2);
                ldm_x4(bl[nb], rb + T_B_LO*2);
            }
            #pragma unroll
            for (int mf = 0; mf < 2; mf++)
                #pragma unroll
                for (int nb = 0; nb < 4; nb++)
                    #pragma unroll
                    for (int sub = 0; sub < 2; sub++) {
                        float* c = acc[mf][nb*2 + sub];
                        mma_bf16(c, ah[mf], bh[nb][sub], bh[nb][sub+2]);
                        mma_bf16(c, ah[mf], bl[nb][sub], bl[nb][sub+2]);
                        mma_bf16(c, al[mf], bh[nb][sub], bh[nb][sub+2]);
                    }
        }
        __syncthreads();
    }

    // ---- epilogue ----
    const int g = lane >> 2, t = lane & 3;
    #pragma unroll
    for (int mf = 0; mf < 2; mf++) {
        const int r0 = m0 + wm*32 + mf*16 + g;
        const int r1 = r0 + 8;
        const int bb0 = r0 >> 11, pos0 = r0 & 2047;
        const int bb1 = r1 >> 11, pos1 = r1 & 2047;
        #pragma unroll
        for (int nf = 0; nf < 8; nf++) {
            const int col = n0 + wn*64 + nf*8 + 2*t;
            float b0 = bias[col], b1 = bias[col + 1];
            float v00 = acc[mf][nf][0] + b0, v01 = acc[mf][nf][1] + b1;
            float v10 = acc[mf][nf][2] + b0, v11 = acc[mf][nf][3] + b1;
            if (MODE == 2 || MODE == 3) {
                const int p = (col & 127) >> 1;
                float cs0 = g_cos[pos0*64 + p], sn0 = g_sin[pos0*64 + p];
                float cs1 = g_cos[pos1*64 + p], sn1 = g_sin[pos1*64 + p];
                float x1 = v00, x2 = v01;
                v00 = x1*cs0 - x2*sn0;  v01 = x1*sn0 + x2*cs0;
                x1 = v10; x2 = v11;
                v10 = x1*cs1 - x2*sn1;  v11 = x1*sn1 + x2*cs1;
                if (MODE == 2) { v00 *= QK_SCALE; v01 *= QK_SCALE; v10 *= QK_SCALE; v11 *= QK_SCALE; }
            }
            if (MODE == 0) {
                *(float2*)(outp + (size_t)r0 * 2048 + col) = make_float2(v00, v01);
                *(float2*)(outp + (size_t)r1 * 2048 + col) = make_float2(v10, v11);
            } else {
                __nv_bfloat16 *dhi, *dlo;
                if      (MODE == 2) { dhi = g_qhi; dlo = g_qlo; }
                else if (MODE == 3) { dhi = g_khi; dlo = g_klo; }
                else                { dhi = g_vhi; dlo = g_vlo; }
                const int h = col >> 7, d = col & 127;
                size_t base0 = (((size_t)(bb0*NHEADS + h) * SEQLEN + pos0) * DHEAD + d);
                size_t base1 = (((size_t)(bb1*NHEADS + h) * SEQLEN + pos1) * DHEAD + d);
                __nv_bfloat16 h00 = __float2bfloat16(v00), h01 = __float2bfloat16(v01);
                __nv_bfloat16 h10 = __float2bfloat16(v10), h11 = __float2bfloat16(v11);
                __nv_bfloat162 hp0; hp0.x = h00; hp0.y = h01;
                __nv_bfloat162 hp1; hp1.x = h10; hp1.y = h11;
                *(__nv_bfloat162*)(dhi + base0) = hp0;
                *(__nv_bfloat162*)(dhi + base1) = hp1;
                __nv_bfloat162 lp0, lp1;
                lp0.x = __float2bfloat16(v00 - __bfloat162float(h00));
                lp0.y = __float2bfloat16(v01 - __bfloat162float(h01));
                lp1.x = __float2bfloat16(v10 - __bfloat162float(h10));
                lp1.y = __float2bfloat16(v11 - __bfloat162float(h11));
                *(__nv_bfloat162*)(dlo + base0) = lp0;
                *(__nv_bfloat162*)(dlo + base1) = lp1;
            }
        }
    }
}

// ---------------- tensor-core flash attention --------------------------------------
// grid (16 q-tiles, 32 bh), 256 threads = 8 warps x 16 q-rows. BQ=128, BKV=64.
// S = Qhi*Khi + Qhi*Klo + Qlo*Khi (Q pre-scaled); PV = Phi*Vhi + Phi*Vlo + Plo*Vhi.
#define KVLD    136                          // halves per row (128 + 8 pad)
#define TILE_H  (64*KVLD)                    // 8704 halves per sub-tile
#define BUF_H   (4*TILE_H)                   // Khi,Klo,Vhi,Vlo
#define QLO_OFF (128*KVLD)                   // Q staging: lo after hi
#define SM_ATTN_BYTES (2*BUF_H*2)            // 139264 B

__global__ void __launch_bounds__(256, 1)
attn_mma()
{
    extern __shared__ __nv_bfloat16 smn[];
    const uint32_t sb = smem_u32(smn);
    const int tid = threadIdx.x, lane = tid & 31, w = tid >> 5;
    const int bh = blockIdx.y;
    const int qt = 15 - blockIdx.x;          // heavy tiles first
    const int q0 = qt * 128;

    const size_t qoff = ((size_t)bh * SEQLEN + q0) * DHEAD;
    const __nv_bfloat16* Qhg = g_qhi + qoff;
    const __nv_bfloat16* Qlg = g_qlo + qoff;

    // ---- stage Q (128x128 hi+lo) into smem, build A-frags ----
    for (int idx = tid; idx < 2048; idx += 256) {
        int row = idx >> 4, c = idx & 15;
        uint32_t off = (uint32_t)(row * KVLD + c * 8) * 2;
        cp16(sb + off,             Qhg + row * 128 + c * 8);
        cp16(sb + QLO_OFF*2 + off, Qlg + row * 128 + c * 8);
    }
    CP_COMMIT(); CP_WAIT(0);
    __syncthreads();

    uint32_t qh[8][4], ql[8][4];
    const int lr = lane & 15, lhb = lane >> 4;
    #pragma unroll
    for (int kk = 0; kk < 8; kk++) {
        uint32_t ra = sb + (uint32_t)((w*16 + lr) * KVLD + kk*16 + lhb*8) * 2;
        ldm_x4(qh[kk], ra);
        ldm_x4(ql[kk], ra + QLO_OFF*2);
    }
    __syncthreads();     // Q consumed; smem now reusable for K/V

    // ---- K/V tile loader ----
    auto load_kv = [&](int jt, int buf) {
        const size_t koff = ((size_t)bh * SEQLEN + jt * 64) * DHEAD;
        const __nv_bfloat16* Kh = g_khi + koff;
        const __nv_bfloat16* Kl = g_klo + koff;
        const __nv_bfloat16* Vh = g_vhi + koff;
        const __nv_bfloat16* Vl = g_vlo + koff;
        const uint32_t base = sb + buf * BUF_H * 2;
        for (int idx = tid; idx < 1024; idx += 256) {
            int row = idx >> 4, c = idx & 15;
            uint32_t off = (uint32_t)(row * KVLD + c * 8) * 2;
            int so = row * 128 + c * 8;
            cp16(base + off,              Kh + so);
            cp16(base + TILE_H*2 + off,   Kl + so);
            cp16(base + 2*TILE_H*2 + off, Vh + so);
            cp16(base + 3*TILE_H*2 + off, Vl + so);
        }
    };

    // ---- state ----
    float m_[2] = {-INFINITY, -INFINITY};
    float l_[2] = {0.f, 0.f};
    float o[16][4];
    #pragma unroll
    for (int i = 0; i < 16; i++)
        #pragma unroll
        for (int j = 0; j < 4; j++) o[i][j] = 0.f;

    const int g  = lane >> 2, t2 = (lane & 3) * 2;
    const int wrow0 = q0 + w * 16;
    const int row0  = wrow0 + g;            // per-lane rows: row0, row0+8

    const int ntiles = 2 * qt + 2;
    load_kv(0, 0); CP_COMMIT();

    for (int jt = 0; jt < ntiles; jt++) {
        const int buf = jt & 1;
        const int kv0 = jt * 64;
        if (jt + 1 < ntiles) { load_kv(jt + 1, buf ^ 1); CP_COMMIT(); CP_WAIT(1); }
        else                 { CP_WAIT(0); }
        __syncthreads();

        const bool skip = (wrow0 + 15 < kv0);   // warp entirely above diagonal
        if (!skip) {
            const uint32_t base = sb + buf * BUF_H * 2;

            // ---- S = Q K^T (3-term split) ----
            float s[8][4];
            #pragma unroll
            for (int i = 0; i < 8; i++)
                #pragma unroll
                for (int j = 0; j < 4; j++) s[i][j] = 0.f;

            #pragma unroll
            for (int kk = 0; kk < 8; kk++) {
                #pragma unroll
                for (int nb = 0; nb < 4; nb++) {
                    uint32_t kh4[4], kl4[4];
                    uint32_t rb = base + (uint32_t)((nb*16 + lr) * KVLD + kk*16 + lhb*8) * 2;
                    ldm_x4(kh4, rb);
                    ldm_x4(kl4, rb + TILE_H*2);
                    #pragma unroll
                    for (int sub = 0; sub < 2; sub++) {
                        float* c = s[nb*2 + sub];
                        mma_bf16(c, qh[kk], kh4[sub], kh4[sub+2]);
                        mma_bf16(c, qh[kk], kl4[sub], kl4[sub+2]);
                        mma_bf16(c, ql[kk], kh4[sub], kh4[sub+2]);
                    }
                }
            }

            // ---- causal mask ----
            if (kv0 + 63 > wrow0) {
                #pragma unroll
                for (int nf = 0; nf < 8; nf++) {
                    int c0 = kv0 + nf*8 + t2;
                    if (c0     > row0)     s[nf][0] = -1e30f;
                    if (c0 + 1 > row0)     s[nf][1] = -1e30f;
                    if (c0     > row0 + 8) s[nf][2] = -1e30f;
                    if (c0 + 1 > row0 + 8) s[nf][3] = -1e30f;
                }
            }

            // ---- online softmax (registers + quad shfl) ----
            float mx0 = -INFINITY, mx1 = -INFINITY;
            #pragma unroll
            for (int nf = 0; nf < 8; nf++) {
                mx0 = fmaxf(mx0, fmaxf(s[nf][0], s[nf][1]));
                mx1 = fmaxf(mx1, fmaxf(s[nf][2], s[nf][3]));
            }
            mx0 = fmaxf(mx0, __shfl_xor_sync(0xffffffffu, mx0, 1));
            mx0 = fmaxf(mx0, __shfl_xor_sync(0xffffffffu, mx0, 2));
            mx1 = fmaxf(mx1, __shfl_xor_sync(0xffffffffu, mx1, 1));
            mx1 = fmaxf(mx1, __shfl_xor_sync(0xffffffffu, mx1, 2));
            float mn0 = fmaxf(m_[0], mx0), mn1 = fmaxf(m_[1], mx1);
            float f0 = __expf(m_[0] - mn0), f1 = __expf(m_[1] - mn1);
            m_[0] = mn0; m_[1] = mn1;

            float sum0 = 0.f, sum1 = 0.f;
            #pragma unroll
            for (int nf = 0; nf < 8; nf++) {
                s[nf][0] = __expf(s[nf][0] - mn0); sum0 += s[nf][0];
                s[nf][1] = __expf(s[nf][1] - mn0); sum0 += s[nf][1];
                s[nf][2] = __expf(s[nf][2] - mn1); sum1 += s[nf][2];
                s[nf][3] = __expf(s[nf][3] - mn1); sum1 += s[nf][3];
            }
            sum0 += __shfl_xor_sync(0xffffffffu, sum0, 1);
            sum0 += __shfl_xor_sync(0xffffffffu, sum0, 2);
            sum1 += __shfl_xor_sync(0xffffffffu, sum1, 1);
            sum1 += __shfl_xor_sync(0xffffffffu, sum1, 2);
            l_[0] = l_[0] * f0 + sum0;
            l_[1] = l_[1] * f1 + sum1;

            #pragma unroll
            for (int nf = 0; nf < 16; nf++) {
                o[nf][0] *= f0; o[nf][1] *= f0;
                o[nf][2] *= f1; o[nf][3] *= f1;
            }

            // ---- pack P (hi/lo split) as A-frags ----
            uint32_t ph[4][4], pl[4][4];
            #pragma unroll
            for (int kf = 0; kf < 4; kf++) {
                #pragma unroll
                for (int j = 0; j < 4; j++) {
                    int nf = 2*kf + (j >> 1);
                    int c0 = (j & 1) * 2;             // 0 -> (c0,c1), 1 -> (c2,c3)
                    float p0 = s[nf][c0], p1 = s[nf][c0 + 1];
                    __nv_bfloat16 b0 = __float2bfloat16(p0), b1 = __float2bfloat16(p1);
                    __nv_bfloat162 hb; hb.x = b0; hb.y = b1;
                    ph[kf][j] = *(uint32_t*)&hb;
                    pl[kf][j] = packbf2(p0 - __bfloat162float(b0), p1 - __bfloat162float(b1));
                }
            }
            // fix frag order: need a0=(row g, k0-7)=nf even c0c1, a1=(row g+8, k0-7)=nf even c2c3,
            //                 a2=(row g, k8-15)=nf odd c0c1,  a3=(row g+8, k8-15)=nf odd c2c3
            // mapping above: j=0 ->(nf even, c0c1)=a0 ; j=1 ->(nf even,c2c3)=a1 ;
            //                j=2 ->(nf odd, c0c1)=a2 ; j=3 ->(nf odd,c2c3)=a3   ✓

            // ---- O += P V (3-term split) ----
            const uint32_t vbase = base + 2*TILE_H*2;
            const int matv = lane >> 3, jv = lane & 7;
            #pragma unroll
            for (int kf = 0; kf < 4; kf++) {
                #pragma unroll
                for (int ng = 0; ng < 8; ng++) {
                    uint32_t vh4[4], vl4[4];
                    uint32_t va = vbase + (uint32_t)((kf*16 + jv + ((matv & 1) << 3)) * KVLD
                                                    + ng*16 + ((matv >> 1) << 3)) * 2;
                    ldm_x4_t(vh4, va);
                    ldm_x4_t(vl4, va + TILE_H*2);
                    #pragma unroll
                    for (int sub = 0; sub < 2; sub++) {
                        float* c = o[ng*2 + sub];
                        mma_bf16(c, ph[kf], vh4[sub*2], vh4[sub*2+1]);
                        mma_bf16(c, ph[kf], vl4[sub*2], vl4[sub*2+1]);
                        mma_bf16(c, pl[kf], vh4[sub*2], vh4[sub*2+1]);
                    }
                }
            }
        }
        __syncthreads();
    }

    // ---- epilogue: normalize, split to bf16 hi/lo, write x-layout ----
    const float inv0 = 1.f / l_[0];
    const float inv1 = 1.f / l_[1];
    const int bb = bh >> 4, h = bh & 15;
    const size_t rA0 = (size_t)(bb * SEQLEN + row0) * D_MODEL + h * DHEAD;
    const size_t rA1 = rA0 + 8 * D_MODEL;
    #pragma unroll
    for (int nf = 0; nf < 16; nf++) {
        int d = nf*8 + t2;
        float v00 = o[nf][0]*inv0, v01 = o[nf][1]*inv0;
        float v10 = o[nf][2]*inv1, v11 = o[nf][3]*inv1;
        __nv_bfloat16 h00 = __float2bfloat16(v00), h01 = __float2bfloat16(v01);
        __nv_bfloat16 h10 = __float2bfloat16(v10), h11 = __float2bfloat16(v11);
        __nv_bfloat162 hp0; hp0.x = h00; hp0.y = h01;
        __nv_bfloat162 hp1; hp1.x = h10; hp1.y = h11;
        *(__nv_bfloat162*)(g_ahi + rA0 + d) = hp0;
        *(__nv_bfloat162*)(g_ahi + rA1 + d) = hp1;
        __nv_bfloat162 lp0, lp1;
        lp0.x = __float2bfloat16(v00 - __bfloat162float(h00));
        lp0.y = __float2bfloat16(v01 - __bfloat162float(h01));
        lp1.x = __float2bfloat16(v10 - __bfloat162float(h10));
        lp1.y = __float2bfloat16(v11 - __bfloat162float(h11));
        *(__nv_bfloat162*)(g_alo + rA0 + d) = lp0;
        *(__nv_bfloat162*)(g_alo + rA1 + d) = lp1;
    }
}

// ---------------- launch -----------------------------------------------------------
extern "C" void kernel_launch(void* const* d_in, const int* in_sizes, int n_in,
                              void* d_out, int out_size)
{
    const float* x  = (const float*)d_in[0];
    const float* Wq = (const float*)d_in[1];
    const float* bq = (const float*)d_in[2];
    const float* Wk = (const float*)d_in[3];
    const float* bk = (const float*)d_in[4];
    const float* Wv = (const float*)d_in[5];
    const float* bv = (const float*)d_in[6];
    const float* Wo = (const float*)d_in[7];
    const float* bo = (const float*)d_in[8];
    float* out = (float*)d_out;

    cudaFuncSetAttribute(attn_mma,    cudaFuncAttributeMaxDynamicSharedMemorySize, SM_ATTN_BYTES);
    cudaFuncSetAttribute(gemm_mma<0>, cudaFuncAttributeMaxDynamicSharedMemorySize, SMEM_GEMM_BYTES);
    cudaFuncSetAttribute(gemm_mma<1>, cudaFuncAttributeMaxDynamicSharedMemorySize, SMEM_GEMM_BYTES);
    cudaFuncSetAttribute(gemm_mma<2>, cudaFuncAttributeMaxDynamicSharedMemorySize, SMEM_GEMM_BYTES);
    cudaFuncSetAttribute(gemm_mma<3>, cudaFuncAttributeMaxDynamicSharedMemorySize, SMEM_GEMM_BYTES);

    rope_table_kernel<<<512, 256>>>();

    const int NX = MROWS * D_MODEL;
    const int NW = D_MODEL * D_MODEL;
    split_kernel<0><<<NX/256, 256>>>(x,  NX);
    split_kernel<1><<<NW/256, 256>>>(Wq, NW);
    split_kernel<2><<<NW/256, 256>>>(Wk, NW);
    split_kernel<3><<<NW/256, 256>>>(Wv, NW);
    split_kernel<4><<<NW/256, 256>>>(Wo, NW);

    dim3 gg(16, 32);   // (N/128, M/128)
    gemm_mma<2><<<gg, 256, SMEM_GEMM_BYTES>>>(bq, nullptr);  // Q (+RoPE, scaled)
    gemm_mma<3><<<gg, 256, SMEM_GEMM_BYTES>>>(bk, nullptr);  // K (+RoPE)
    gemm_mma<1><<<gg, 256, SMEM_GEMM_BYTES>>>(bv, nullptr);  // V

    attn_mma<<<dim3(16, 32), 256, SM_ATTN_BYTES>>>();

    gemm_mma<0><<<gg, 256, SMEM_GEMM_BYTES>>>(bo, out);      // output projection
}

// round 7
// speedup vs baseline: 2.8179x; 1.1586x over previous
#include <cuda_runtime.h>
#include <cuda_bf16.h>
#include <math.h>
#include <stdint.h>

#define D_MODEL 2048
#define NHEADS  16
#define DHEAD   128
#define SEQLEN  2048
#define BATCH   2
#define MROWS   (BATCH*SEQLEN)   // 4096
#define QK_SCALE 0.08838834764831845f   // 1/sqrt(128)

// ---------------- scratch (device globals; no allocation allowed) ----------------
__device__ float g_cos[SEQLEN*(DHEAD/2)];
__device__ float g_sin[SEQLEN*(DHEAD/2)];

__device__ __nv_bfloat16 g_xhi[MROWS*D_MODEL];
__device__ __nv_bfloat16 g_xlo[MROWS*D_MODEL];
__device__ __nv_bfloat16 g_whi[4][D_MODEL*D_MODEL];   // 0=Wq 1=Wk 2=Wv 3=Wo
__device__ __nv_bfloat16 g_wlo[4][D_MODEL*D_MODEL];
__device__ __nv_bfloat16 g_ahi[MROWS*D_MODEL];        // attention out, x-layout
__device__ __nv_bfloat16 g_alo[MROWS*D_MODEL];
__device__ __nv_bfloat16 g_qhi[BATCH*NHEADS*SEQLEN*DHEAD];
__device__ __nv_bfloat16 g_qlo[BATCH*NHEADS*SEQLEN*DHEAD];
__device__ __nv_bfloat16 g_khi[BATCH*NHEADS*SEQLEN*DHEAD];
__device__ __nv_bfloat16 g_klo[BATCH*NHEADS*SEQLEN*DHEAD];
__device__ __nv_bfloat16 g_vhi[BATCH*NHEADS*SEQLEN*DHEAD];
__device__ __nv_bfloat16 g_vlo[BATCH*NHEADS*SEQLEN*DHEAD];

// ---------------- PTX helpers (sm_80-level only) -----------------------------------
__device__ __forceinline__ uint32_t smem_u32(const void* p) {
    uint32_t a;
    asm("{ .reg .u64 t; cvta.to.shared.u64 t, %1; cvt.u32.u64 %0, t; }" : "=r"(a) : "l"(p));
    return a;
}
__device__ __forceinline__ void cp16(uint32_t dst, const void* src) {
    asm volatile("cp.async.cg.shared.global [%0], [%1], 16;" :: "r"(dst), "l"(src));
}
#define CP_COMMIT() asm volatile("cp.async.commit_group;" ::: "memory")
#define CP_WAIT(n)  asm volatile("cp.async.wait_group %0;" :: "n"(n) : "memory")

__device__ __forceinline__ void ldm_x4(uint32_t* r, uint32_t addr) {
    asm volatile("ldmatrix.sync.aligned.m8n8.x4.shared.b16 {%0,%1,%2,%3}, [%4];"
                 : "=r"(r[0]), "=r"(r[1]), "=r"(r[2]), "=r"(r[3]) : "r"(addr));
}
__device__ __forceinline__ void ldm_x4_t(uint32_t* r, uint32_t addr) {
    asm volatile("ldmatrix.sync.aligned.m8n8.x4.trans.shared.b16 {%0,%1,%2,%3}, [%4];"
                 : "=r"(r[0]), "=r"(r[1]), "=r"(r[2]), "=r"(r[3]) : "r"(addr));
}
__device__ __forceinline__ void mma_bf16(float* c, const uint32_t* a, uint32_t b0, uint32_t b1) {
    asm volatile("mma.sync.aligned.m16n8k16.row.col.f32.bf16.bf16.f32 "
                 "{%0,%1,%2,%3}, {%4,%5,%6,%7}, {%8,%9}, {%0,%1,%2,%3};"
                 : "+f"(c[0]), "+f"(c[1]), "+f"(c[2]), "+f"(c[3])
                 : "r"(a[0]), "r"(a[1]), "r"(a[2]), "r"(a[3]), "r"(b0), "r"(b1));
}
__device__ __forceinline__ uint32_t packbf2(float lo, float hi) {
    uint32_t r;
    asm("cvt.rn.bf16x2.f32 %0, %1, %2;" : "=r"(r) : "f"(hi), "f"(lo));
    return r;
}

// ---------------- RoPE tables ------------------------------------------------------
__global__ void rope_table_kernel() {
    int idx = blockIdx.x * blockDim.x + threadIdx.x;
    int pos = idx >> 6;
    int p   = idx & 63;
    double freq = exp(-((double)(2 * p) / 128.0) * log(10000.0));
    double ang  = (double)pos * freq;
    g_cos[idx] = (float)cos(ang);
    g_sin[idx] = (float)sin(ang);
}

// ---------------- hi/lo bf16 split kernels -----------------------------------------
__global__ void split_x_kernel(const float* __restrict__ src) {
    int i = blockIdx.x * 256 + threadIdx.x;
    float v = src[i];
    __nv_bfloat16 h = __float2bfloat16(v);
    g_xhi[i] = h;
    g_xlo[i] = __float2bfloat16(v - __bfloat162float(h));
}
// grid (NW/256, 4): y selects which weight
__global__ void split_w_kernel(const float* __restrict__ w0, const float* __restrict__ w1,
                               const float* __restrict__ w2, const float* __restrict__ w3) {
    int i = blockIdx.x * 256 + threadIdx.x;
    int wsel = blockIdx.y;
    const float* s = (wsel == 0) ? w0 : (wsel == 1) ? w1 : (wsel == 2) ? w2 : w3;
    float v = s[i];
    __nv_bfloat16 h = __float2bfloat16(v);
    g_whi[wsel][i] = h;
    g_wlo[wsel][i] = __float2bfloat16(v - __bfloat162float(h));
}

// ---------------- mma.sync split-bf16 GEMM core ------------------------------------
// BM=BN=128, BK=32, 256 threads (8 warps, 4m x 2n), 2-stage pipe, occupancy 2.
#define GLD 40
#define T_A_HI 0
#define T_A_LO (128*GLD)
#define T_B_HI (2*128*GLD)
#define T_B_LO (3*128*GLD)
#define STAGE_HALVES (4*128*GLD)              // 20480 halves = 40960 B
#define SMEM_GEMM_BYTES (2*STAGE_HALVES*2)    // 81920 B

struct GemmCore {
    uint32_t sb;
    int tid, lane, warp, wm, wn, lrow, lc, lr, lh;
    const __nv_bfloat16 *pAh, *pAl, *pBh, *pBl;

    __device__ __forceinline__ void init(uint32_t sb_, int m0, int n0,
                                         const __nv_bfloat16* Ahi, const __nv_bfloat16* Alo,
                                         const __nv_bfloat16* Bhi, const __nv_bfloat16* Blo) {
        sb = sb_; tid = threadIdx.x;
        lane = tid & 31; warp = tid >> 5;
        wm = warp & 3; wn = warp >> 2;
        lrow = tid & 127; lc = tid >> 7;
        lr = lane & 15; lh = lane >> 4;
        pAh = Ahi + (size_t)(m0 + lrow) * 2048;
        pAl = Alo + (size_t)(m0 + lrow) * 2048;
        pBh = Bhi + (size_t)(n0 + lrow) * 2048;
        pBl = Blo + (size_t)(n0 + lrow) * 2048;
    }
    __device__ __forceinline__ void load_stage(int s, int buf) {
        const int k0 = s * 32;
        const uint32_t base = sb + buf * STAGE_HALVES * 2;
        #pragma unroll
        for (int q = 0; q < 2; q++) {
            const int c = lc + q * 2;
            const uint32_t off = (lrow * GLD + c * 8) * 2;
            const int ks = k0 + c * 8;
            cp16(base + T_A_HI*2 + off, pAh + ks);
            cp16(base + T_A_LO*2 + off, pAl + ks);
            cp16(base + T_B_HI*2 + off, pBh + ks);
            cp16(base + T_B_LO*2 + off, pBl + ks);
        }
    }
    __device__ __forceinline__ void run(float acc[2][8][4]) {
        load_stage(0, 0); CP_COMMIT();
        for (int s = 0; s < 64; s++) {
            if (s + 1 < 64) { load_stage(s + 1, (s + 1) & 1); CP_COMMIT(); CP_WAIT(1); }
            else            { CP_WAIT(0); }
            __syncthreads();
            const uint32_t base = sb + (s & 1) * STAGE_HALVES * 2;
            #pragma unroll
            for (int kk = 0; kk < 32; kk += 16) {
                uint32_t ah[2][4], al[2][4], bh[4][4], bl[4][4];
                #pragma unroll
                for (int mf = 0; mf < 2; mf++) {
                    uint32_t ra = base + ((wm*32 + mf*16 + lr) * GLD + kk + lh*8) * 2;
                    ldm_x4(ah[mf], ra + T_A_HI*2);
                    ldm_x4(al[mf], ra + T_A_LO*2);
                }
                #pragma unroll
                for (int nb = 0; nb < 4; nb++) {
                    uint32_t rb = base + ((wn*64 + nb*16 + lr) * GLD + kk + lh*8) * 2;
                    ldm_x4(bh[nb], rb + T_B_HI*2);
                    ldm_x4(bl[nb], rb + T_B_LO*2);
                }
                #pragma unroll
                for (int mf = 0; mf < 2; mf++)
                    #pragma unroll
                    for (int nb = 0; nb < 4; nb++)
                        #pragma unroll
                        for (int sub = 0; sub < 2; sub++) {
                            float* c = acc[mf][nb*2 + sub];
                            mma_bf16(c, ah[mf], bh[nb][sub], bh[nb][sub+2]);
                            mma_bf16(c, ah[mf], bl[nb][sub], bl[nb][sub+2]);
                            mma_bf16(c, al[mf], bh[nb][sub], bh[nb][sub+2]);
                        }
            }
            __syncthreads();
        }
    }
};

// ---- fused Q/K/V projection: grid (16, 32, 3), z: 0=Q 1=K 2=V ----------------------
__global__ void __launch_bounds__(256, 2)
qkv_mma(const float* __restrict__ bq, const float* __restrict__ bk,
        const float* __restrict__ bv)
{
    extern __shared__ __nv_bfloat16 smem[];
    const int m0 = blockIdx.y * 128;
    const int n0 = blockIdx.x * 128;
    const int z  = blockIdx.z;               // 0=Q 1=K 2=V

    GemmCore core;
    core.init(smem_u32(smem), m0, n0, g_xhi, g_xlo, g_whi[z], g_wlo[z]);

    float acc[2][8][4];
    #pragma unroll
    for (int i = 0; i < 2; i++)
        #pragma unroll
        for (int j = 0; j < 8; j++)
            #pragma unroll
            for (int k = 0; k < 4; k++) acc[i][j][k] = 0.f;

    core.run(acc);

    const float* bias = (z == 0) ? bq : (z == 1) ? bk : bv;
    __nv_bfloat16* dhi = (z == 0) ? g_qhi : (z == 1) ? g_khi : g_vhi;
    __nv_bfloat16* dlo = (z == 0) ? g_qlo : (z == 1) ? g_klo : g_vlo;
    const bool do_rope = (z != 2);
    const float sc = (z == 0) ? QK_SCALE : 1.0f;

    const int g = core.lane >> 2, t = core.lane & 3;
    #pragma unroll
    for (int mf = 0; mf < 2; mf++) {
        const int r0 = m0 + core.wm*32 + mf*16 + g;
        const int r1 = r0 + 8;
        const int bb0 = r0 >> 11, pos0 = r0 & 2047;
        const int bb1 = r1 >> 11, pos1 = r1 & 2047;
        #pragma unroll
        for (int nf = 0; nf < 8; nf++) {
            const int col = n0 + core.wn*64 + nf*8 + 2*t;
            float b0 = bias[col], b1 = bias[col + 1];
            float v00 = acc[mf][nf][0] + b0, v01 = acc[mf][nf][1] + b1;
            float v10 = acc[mf][nf][2] + b0, v11 = acc[mf][nf][3] + b1;
            if (do_rope) {
                const int p = (col & 127) >> 1;
                float cs0 = g_cos[pos0*64 + p], sn0 = g_sin[pos0*64 + p];
                float cs1 = g_cos[pos1*64 + p], sn1 = g_sin[pos1*64 + p];
                float x1 = v00, x2 = v01;
                v00 = (x1*cs0 - x2*sn0) * sc;  v01 = (x1*sn0 + x2*cs0) * sc;
                x1 = v10; x2 = v11;
                v10 = (x1*cs1 - x2*sn1) * sc;  v11 = (x1*sn1 + x2*cs1) * sc;
            }
            const int h = col >> 7, d = col & 127;
            size_t base0 = (((size_t)(bb0*NHEADS + h) * SEQLEN + pos0) * DHEAD + d);
            size_t base1 = (((size_t)(bb1*NHEADS + h) * SEQLEN + pos1) * DHEAD + d);
            __nv_bfloat16 h00 = __float2bfloat16(v00), h01 = __float2bfloat16(v01);
            __nv_bfloat16 h10 = __float2bfloat16(v10), h11 = __float2bfloat16(v11);
            __nv_bfloat162 hp0; hp0.x = h00; hp0.y = h01;
            __nv_bfloat162 hp1; hp1.x = h10; hp1.y = h11;
            *(__nv_bfloat162*)(dhi + base0) = hp0;
            *(__nv_bfloat162*)(dhi + base1) = hp1;
            __nv_bfloat162 lp0, lp1;
            lp0.x = __float2bfloat16(v00 - __bfloat162float(h00));
            lp0.y = __float2bfloat16(v01 - __bfloat162float(h01));
            lp1.x = __float2bfloat16(v10 - __bfloat162float(h10));
            lp1.y = __float2bfloat16(v11 - __bfloat162float(h11));
            *(__nv_bfloat162*)(dlo + base0) = lp0;
            *(__nv_bfloat162*)(dlo + base1) = lp1;
        }
    }
}

// ---- output projection: reads g_ahi/alo, writes fp32 d_out -------------------------
__global__ void __launch_bounds__(256, 2)
out_mma(const float* __restrict__ bias, float* __restrict__ outp)
{
    extern __shared__ __nv_bfloat16 smem[];
    const int m0 = blockIdx.y * 128;
    const int n0 = blockIdx.x * 128;

    GemmCore core;
    core.init(smem_u32(smem), m0, n0, g_ahi, g_alo, g_whi[3], g_wlo[3]);

    float acc[2][8][4];
    #pragma unroll
    for (int i = 0; i < 2; i++)
        #pragma unroll
        for (int j = 0; j < 8; j++)
            #pragma unroll
            for (int k = 0; k < 4; k++) acc[i][j][k] = 0.f;

    core.run(acc);

    const int g = core.lane >> 2, t = core.lane & 3;
    #pragma unroll
    for (int mf = 0; mf < 2; mf++) {
        const int r0 = m0 + core.wm*32 + mf*16 + g;
        const int r1 = r0 + 8;
        #pragma unroll
        for (int nf = 0; nf < 8; nf++) {
            const int col = n0 + core.wn*64 + nf*8 + 2*t;
            float b0 = bias[col], b1 = bias[col + 1];
            *(float2*)(outp + (size_t)r0 * 2048 + col) =
                make_float2(acc[mf][nf][0] + b0, acc[mf][nf][1] + b1);
            *(float2*)(outp + (size_t)r1 * 2048 + col) =
                make_float2(acc[mf][nf][2] + b0, acc[mf][nf][3] + b1);
        }
    }
}

// ---------------- tensor-core flash attention (unchanged from R6) ------------------
#define KVLD    136
#define TILE_H  (64*KVLD)
#define BUF_H   (4*TILE_H)
#define QLO_OFF (128*KVLD)
#define SM_ATTN_BYTES (2*BUF_H*2)            // 139264 B

__global__ void __launch_bounds__(256, 1)
attn_mma()
{
    extern __shared__ __nv_bfloat16 smn[];
    const uint32_t sb = smem_u32(smn);
    const int tid = threadIdx.x, lane = tid & 31, w = tid >> 5;
    const int bh = blockIdx.y;
    const int qt = 15 - blockIdx.x;
    const int q0 = qt * 128;

    const size_t qoff = ((size_t)bh * SEQLEN + q0) * DHEAD;
    const __nv_bfloat16* Qhg = g_qhi + qoff;
    const __nv_bfloat16* Qlg = g_qlo + qoff;

    for (int idx = tid; idx < 2048; idx += 256) {
        int row = idx >> 4, c = idx & 15;
        uint32_t off = (uint32_t)(row * KVLD + c * 8) * 2;
        cp16(sb + off,             Qhg + row * 128 + c * 8);
        cp16(sb + QLO_OFF*2 + off, Qlg + row * 128 + c * 8);
    }
    CP_COMMIT(); CP_WAIT(0);
    __syncthreads();

    uint32_t qh[8][4], ql[8][4];
    const int lr = lane & 15, lhb = lane >> 4;
    #pragma unroll
    for (int kk = 0; kk < 8; kk++) {
        uint32_t ra = sb + (uint32_t)((w*16 + lr) * KVLD + kk*16 + lhb*8) * 2;
        ldm_x4(qh[kk], ra);
        ldm_x4(ql[kk], ra + QLO_OFF*2);
    }
    __syncthreads();

    auto load_kv = [&](int jt, int buf) {
        const size_t koff = ((size_t)bh * SEQLEN + jt * 64) * DHEAD;
        const __nv_bfloat16* Kh = g_khi + koff;
        const __nv_bfloat16* Kl = g_klo + koff;
        const __nv_bfloat16* Vh = g_vhi + koff;
        const __nv_bfloat16* Vl = g_vlo + koff;
        const uint32_t base = sb + buf * BUF_H * 2;
        for (int idx = tid; idx < 1024; idx += 256) {
            int row = idx >> 4, c = idx & 15;
            uint32_t off = (uint32_t)(row * KVLD + c * 8) * 2;
            int so = row * 128 + c * 8;
            cp16(base + off,              Kh + so);
            cp16(base + TILE_H*2 + off,   Kl + so);
            cp16(base + 2*TILE_H*2 + off, Vh + so);
            cp16(base + 3*TILE_H*2 + off, Vl + so);
        }
    };

    float m_[2] = {-INFINITY, -INFINITY};
    float l_[2] = {0.f, 0.f};
    float o[16][4];
    #pragma unroll
    for (int i = 0; i < 16; i++)
        #pragma unroll
        for (int j = 0; j < 4; j++) o[i][j] = 0.f;

    const int g  = lane >> 2, t2 = (lane & 3) * 2;
    const int wrow0 = q0 + w * 16;
    const int row0  = wrow0 + g;

    const int ntiles = 2 * qt + 2;
    load_kv(0, 0); CP_COMMIT();

    for (int jt = 0; jt < ntiles; jt++) {
        const int buf = jt & 1;
        const int kv0 = jt * 64;
        if (jt + 1 < ntiles) { load_kv(jt + 1, buf ^ 1); CP_COMMIT(); CP_WAIT(1); }
        else                 { CP_WAIT(0); }
        __syncthreads();

        const bool skip = (wrow0 + 15 < kv0);
        if (!skip) {
            const uint32_t base = sb + buf * BUF_H * 2;

            float s[8][4];
            #pragma unroll
            for (int i = 0; i < 8; i++)
                #pragma unroll
                for (int j = 0; j < 4; j++) s[i][j] = 0.f;

            #pragma unroll
            for (int kk = 0; kk < 8; kk++) {
                #pragma unroll
                for (int nb = 0; nb < 4; nb++) {
                    uint32_t kh4[4], kl4[4];
                    uint32_t rb = base + (uint32_t)((nb*16 + lr) * KVLD + kk*16 + lhb*8) * 2;
                    ldm_x4(kh4, rb);
                    ldm_x4(kl4, rb + TILE_H*2);
                    #pragma unroll
                    for (int sub = 0; sub < 2; sub++) {
                        float* c = s[nb*2 + sub];
                        mma_bf16(c, qh[kk], kh4[sub], kh4[sub+2]);
                        mma_bf16(c, qh[kk], kl4[sub], kl4[sub+2]);
                        mma_bf16(c, ql[kk], kh4[sub], kh4[sub+2]);
                    }
                }
            }

            if (kv0 + 63 > wrow0) {
                #pragma unroll
                for (int nf = 0; nf < 8; nf++) {
                    int c0 = kv0 + nf*8 + t2;
                    if (c0     > row0)     s[nf][0] = -1e30f;
                    if (c0 + 1 > row0)     s[nf][1] = -1e30f;
                    if (c0     > row0 + 8) s[nf][2] = -1e30f;
                    if (c0 + 1 > row0 + 8) s[nf][3] = -1e30f;
                }
            }

            float mx0 = -INFINITY, mx1 = -INFINITY;
            #pragma unroll
            for (int nf = 0; nf < 8; nf++) {
                mx0 = fmaxf(mx0, fmaxf(s[nf][0], s[nf][1]));
                mx1 = fmaxf(mx1, fmaxf(s[nf][2], s[nf][3]));
            }
            mx0 = fmaxf(mx0, __shfl_xor_sync(0xffffffffu, mx0, 1));
            mx0 = fmaxf(mx0, __shfl_xor_sync(0xffffffffu, mx0, 2));
            mx1 = fmaxf(mx1, __shfl_xor_sync(0xffffffffu, mx1, 1));
            mx1 = fmaxf(mx1, __shfl_xor_sync(0xffffffffu, mx1, 2));
            float mn0 = fmaxf(m_[0], mx0), mn1 = fmaxf(m_[1], mx1);
            float f0 = __expf(m_[0] - mn0), f1 = __expf(m_[1] - mn1);
            m_[0] = mn0; m_[1] = mn1;

            float sum0 = 0.f, sum1 = 0.f;
            #pragma unroll
            for (int nf = 0; nf < 8; nf++) {
                s[nf][0] = __expf(s[nf][0] - mn0); sum0 += s[nf][0];
                s[nf][1] = __expf(s[nf][1] - mn0); sum0 += s[nf][1];
                s[nf][2] = __expf(s[nf][2] - mn1); sum1 += s[nf][2];
                s[nf][3] = __expf(s[nf][3] - mn1); sum1 += s[nf][3];
            }
            sum0 += __shfl_xor_sync(0xffffffffu, sum0, 1);
            sum0 += __shfl_xor_sync(0xffffffffu, sum0, 2);
            sum1 += __shfl_xor_sync(0xffffffffu, sum1, 1);
            sum1 += __shfl_xor_sync(0xffffffffu, sum1, 2);
            l_[0] = l_[0] * f0 + sum0;
            l_[1] = l_[1] * f1 + sum1;

            #pragma unroll
            for (int nf = 0; nf < 16; nf++) {
                o[nf][0] *= f0; o[nf][1] *= f0;
                o[nf][2] *= f1; o[nf][3] *= f1;
            }

            uint32_t ph[4][4], pl[4][4];
            #pragma unroll
            for (int kf = 0; kf < 4; kf++) {
                #pragma unroll
                for (int j = 0; j < 4; j++) {
                    int nf = 2*kf + (j >> 1);
                    int c0 = (j & 1) * 2;
                    float p0 = s[nf][c0], p1 = s[nf][c0 + 1];
                    __nv_bfloat16 b0 = __float2bfloat16(p0), b1 = __float2bfloat16(p1);
                    __nv_bfloat162 hb; hb.x = b0; hb.y = b1;
                    ph[kf][j] = *(uint32_t*)&hb;
                    pl[kf][j] = packbf2(p0 - __bfloat162float(b0), p1 - __bfloat162float(b1));
                }
            }

            const uint32_t vbase = base + 2*TILE_H*2;
            const int matv = lane >> 3, jv = lane & 7;
            #pragma unroll
            for (int kf = 0; kf < 4; kf++) {
                #pragma unroll
                for (int ng = 0; ng < 8; ng++) {
                    uint32_t vh4[4], vl4[4];
                    uint32_t va = vbase + (uint32_t)((kf*16 + jv + ((matv & 1) << 3)) * KVLD
                                                    + ng*16 + ((matv >> 1) << 3)) * 2;
                    ldm_x4_t(vh4, va);
                    ldm_x4_t(vl4, va + TILE_H*2);
                    #pragma unroll
                    for (int sub = 0; sub < 2; sub++) {
                        float* c = o[ng*2 + sub];
                        mma_bf16(c, ph[kf], vh4[sub*2], vh4[sub*2+1]);
                        mma_bf16(c, ph[kf], vl4[sub*2], vl4[sub*2+1]);
                        mma_bf16(c, pl[kf], vh4[sub*2], vh4[sub*2+1]);
                    }
                }
            }
        }
        __syncthreads();
    }

    const float inv0 = 1.f / l_[0];
    const float inv1 = 1.f / l_[1];
    const int bb = bh >> 4, h = bh & 15;
    const size_t rA0 = (size_t)(bb * SEQLEN + row0) * D_MODEL + h * DHEAD;
    const size_t rA1 = rA0 + 8 * D_MODEL;
    #pragma unroll
    for (int nf = 0; nf < 16; nf++) {
        int d = nf*8 + t2;
        float v00 = o[nf][0]*inv0, v01 = o[nf][1]*inv0;
        float v10 = o[nf][2]*inv1, v11 = o[nf][3]*inv1;
        __nv_bfloat16 h00 = __float2bfloat16(v00), h01 = __float2bfloat16(v01);
        __nv_bfloat16 h10 = __float2bfloat16(v10), h11 = __float2bfloat16(v11);
        __nv_bfloat162 hp0; hp0.x = h00; hp0.y = h01;
        __nv_bfloat162 hp1; hp1.x = h10; hp1.y = h11;
        *(__nv_bfloat162*)(g_ahi + rA0 + d) = hp0;
        *(__nv_bfloat162*)(g_ahi + rA1 + d) = hp1;
        __nv_bfloat162 lp0, lp1;
        lp0.x = __float2bfloat16(v00 - __bfloat162float(h00));
        lp0.y = __float2bfloat16(v01 - __bfloat162float(h01));
        lp1.x = __float2bfloat16(v10 - __bfloat162float(h10));
        lp1.y = __float2bfloat16(v11 - __bfloat162float(h11));
        *(__nv_bfloat162*)(g_alo + rA0 + d) = lp0;
        *(__nv_bfloat162*)(g_alo + rA1 + d) = lp1;
    }
}

// ---------------- launch -----------------------------------------------------------
extern "C" void kernel_launch(void* const* d_in, const int* in_sizes, int n_in,
                              void* d_out, int out_size)
{
    const float* x  = (const float*)d_in[0];
    const float* Wq = (const float*)d_in[1];
    const float* bq = (const float*)d_in[2];
    const float* Wk = (const float*)d_in[3];
    const float* bk = (const float*)d_in[4];
    const float* Wv = (const float*)d_in[5];
    const float* bv = (const float*)d_in[6];
    const float* Wo = (const float*)d_in[7];
    const float* bo = (const float*)d_in[8];
    float* out = (float*)d_out;

    cudaFuncSetAttribute(attn_mma, cudaFuncAttributeMaxDynamicSharedMemorySize, SM_ATTN_BYTES);
    cudaFuncSetAttribute(qkv_mma,  cudaFuncAttributeMaxDynamicSharedMemorySize, SMEM_GEMM_BYTES);
    cudaFuncSetAttribute(out_mma,  cudaFuncAttributeMaxDynamicSharedMemorySize, SMEM_GEMM_BYTES);

    rope_table_kernel<<<512, 256>>>();

    const int NX = MROWS * D_MODEL;
    const int NW = D_MODEL * D_MODEL;
    split_x_kernel<<<NX/256, 256>>>(x);
    split_w_kernel<<<dim3(NW/256, 4), 256>>>(Wq, Wk, Wv, Wo);

    qkv_mma<<<dim3(16, 32, 3), 256, SMEM_GEMM_BYTES>>>(bq, bk, bv);

    attn_mma<<<dim3(16, 32), 256, SM_ATTN_BYTES>>>();

    out_mma<<<dim3(16, 32), 256, SMEM_GEMM_BYTES>>>(bo, out);
}

// round 8
// speedup vs baseline: 2.8478x; 1.0106x over previous
#include <cuda_runtime.h>
#include <cuda_bf16.h>
#include <math.h>
#include <stdint.h>

#define D_MODEL 2048
#define NHEADS  16
#define DHEAD   128
#define SEQLEN  2048
#define BATCH   2
#define MROWS   (BATCH*SEQLEN)   // 4096
#define QK_SCALE 0.08838834764831845f   // 1/sqrt(128)

// ---------------- scratch (device globals; no allocation allowed) ----------------
__device__ float g_cos[SEQLEN*(DHEAD/2)];
__device__ float g_sin[SEQLEN*(DHEAD/2)];

__device__ __nv_bfloat16 g_xhi[MROWS*D_MODEL];
__device__ __nv_bfloat16 g_xlo[MROWS*D_MODEL];
__device__ __nv_bfloat16 g_whi[4][D_MODEL*D_MODEL];   // 0=Wq 1=Wk 2=Wv 3=Wo
__device__ __nv_bfloat16 g_wlo[4][D_MODEL*D_MODEL];
__device__ __nv_bfloat16 g_ahi[MROWS*D_MODEL];        // attention out, x-layout
__device__ __nv_bfloat16 g_alo[MROWS*D_MODEL];
__device__ __nv_bfloat16 g_qhi[BATCH*NHEADS*SEQLEN*DHEAD];
__device__ __nv_bfloat16 g_qlo[BATCH*NHEADS*SEQLEN*DHEAD];
__device__ __nv_bfloat16 g_khi[BATCH*NHEADS*SEQLEN*DHEAD];
__device__ __nv_bfloat16 g_klo[BATCH*NHEADS*SEQLEN*DHEAD];
__device__ __nv_bfloat16 g_vhi[BATCH*NHEADS*SEQLEN*DHEAD];
__device__ __nv_bfloat16 g_vlo[BATCH*NHEADS*SEQLEN*DHEAD];

// ---------------- PTX helpers (sm_80-level only) -----------------------------------
__device__ __forceinline__ uint32_t smem_u32(const void* p) {
    uint32_t a;
    asm("{ .reg .u64 t; cvta.to.shared.u64 t, %1; cvt.u32.u64 %0, t; }" : "=r"(a) : "l"(p));
    return a;
}
__device__ __forceinline__ void cp16(uint32_t dst, const void* src) {
    asm volatile("cp.async.cg.shared.global [%0], [%1], 16;" :: "r"(dst), "l"(src));
}
#define CP_COMMIT() asm volatile("cp.async.commit_group;" ::: "memory")
#define CP_WAIT(n)  asm volatile("cp.async.wait_group %0;" :: "n"(n) : "memory")

__device__ __forceinline__ void ldm_x4(uint32_t* r, uint32_t addr) {
    asm volatile("ldmatrix.sync.aligned.m8n8.x4.shared.b16 {%0,%1,%2,%3}, [%4];"
                 : "=r"(r[0]), "=r"(r[1]), "=r"(r[2]), "=r"(r[3]) : "r"(addr));
}
__device__ __forceinline__ void ldm_x4_t(uint32_t* r, uint32_t addr) {
    asm volatile("ldmatrix.sync.aligned.m8n8.x4.trans.shared.b16 {%0,%1,%2,%3}, [%4];"
                 : "=r"(r[0]), "=r"(r[1]), "=r"(r[2]), "=r"(r[3]) : "r"(addr));
}
__device__ __forceinline__ void mma_bf16(float* c, const uint32_t* a, uint32_t b0, uint32_t b1) {
    asm volatile("mma.sync.aligned.m16n8k16.row.col.f32.bf16.bf16.f32 "
                 "{%0,%1,%2,%3}, {%4,%5,%6,%7}, {%8,%9}, {%0,%1,%2,%3};"
                 : "+f"(c[0]), "+f"(c[1]), "+f"(c[2]), "+f"(c[3])
                 : "r"(a[0]), "r"(a[1]), "r"(a[2]), "r"(a[3]), "r"(b0), "r"(b1));
}
__device__ __forceinline__ uint32_t packbf2(float lo, float hi) {
    uint32_t r;
    asm("cvt.rn.bf16x2.f32 %0, %1, %2;" : "=r"(r) : "f"(hi), "f"(lo));
    return r;
}

// ---------------- RoPE tables ------------------------------------------------------
__global__ void rope_table_kernel() {
    int idx = blockIdx.x * blockDim.x + threadIdx.x;
    int pos = idx >> 6;
    int p   = idx & 63;
    double freq = exp(-((double)(2 * p) / 128.0) * log(10000.0));
    double ang  = (double)pos * freq;
    g_cos[idx] = (float)cos(ang);
    g_sin[idx] = (float)sin(ang);
}

// ---------------- hi/lo bf16 split kernels -----------------------------------------
__global__ void split_x_kernel(const float* __restrict__ src) {
    int i = blockIdx.x * 256 + threadIdx.x;
    float v = src[i];
    __nv_bfloat16 h = __float2bfloat16(v);
    g_xhi[i] = h;
    g_xlo[i] = __float2bfloat16(v - __bfloat162float(h));
}
__global__ void split_w_kernel(const float* __restrict__ w0, const float* __restrict__ w1,
                               const float* __restrict__ w2, const float* __restrict__ w3) {
    int i = blockIdx.x * 256 + threadIdx.x;
    int wsel = blockIdx.y;
    const float* s = (wsel == 0) ? w0 : (wsel == 1) ? w1 : (wsel == 2) ? w2 : w3;
    float v = s[i];
    __nv_bfloat16 h = __float2bfloat16(v);
    g_whi[wsel][i] = h;
    g_wlo[wsel][i] = __float2bfloat16(v - __bfloat162float(h));
}

// ---------------- mma.sync split-bf16 GEMM core ------------------------------------
// BM=BN=128, BK=16, 256 threads (8 warps, 4m x 2n), 4-stage pipe, occupancy 2.
// GLD=24 halves/row: bank step 12 -> 8 rows hit 8 distinct 4-bank groups (conflict-free).
#define GLD 24
#define T_A_HI 0
#define T_A_LO (128*GLD)
#define T_B_HI (2*128*GLD)
#define T_B_LO (3*128*GLD)
#define STAGE_HALVES (4*128*GLD)              // 12288 halves = 24576 B
#define SMEM_GEMM_BYTES (4*STAGE_HALVES*2)    // 98304 B

struct GemmCore {
    uint32_t sb;
    int lane, wm, wn, lrow, lc, lr, lh;
    const __nv_bfloat16 *pAh, *pAl, *pBh, *pBl;

    __device__ __forceinline__ void init(uint32_t sb_, int m0, int n0,
                                         const __nv_bfloat16* Ahi, const __nv_bfloat16* Alo,
                                         const __nv_bfloat16* Bhi, const __nv_bfloat16* Blo) {
        sb = sb_;
        int tid = threadIdx.x;
        lane = tid & 31;
        int warp = tid >> 5;
        wm = warp & 3; wn = warp >> 2;
        lrow = tid & 127; lc = tid >> 7;
        lr = lane & 15; lh = lane >> 4;
        pAh = Ahi + (size_t)(m0 + lrow) * 2048;
        pAl = Alo + (size_t)(m0 + lrow) * 2048;
        pBh = Bhi + (size_t)(n0 + lrow) * 2048;
        pBl = Blo + (size_t)(n0 + lrow) * 2048;
    }
    __device__ __forceinline__ void load_stage(int s, int buf) {
        const int ks = s * 16 + lc * 8;
        const uint32_t base = sb + buf * STAGE_HALVES * 2;
        const uint32_t off = (lrow * GLD + lc * 8) * 2;
        cp16(base + T_A_HI*2 + off, pAh + ks);
        cp16(base + T_A_LO*2 + off, pAl + ks);
        cp16(base + T_B_HI*2 + off, pBh + ks);
        cp16(base + T_B_LO*2 + off, pBl + ks);
    }
    __device__ __forceinline__ void run(float acc[2][8][4]) {
        load_stage(0, 0); CP_COMMIT();
        load_stage(1, 1); CP_COMMIT();
        load_stage(2, 2); CP_COMMIT();
        for (int s = 0; s < 128; s++) {
            if (s + 3 < 128) { load_stage(s + 3, (s + 3) & 3); CP_COMMIT(); }
            if      (s < 125)  CP_WAIT(3);
            else if (s == 125) CP_WAIT(2);
            else if (s == 126) CP_WAIT(1);
            else               CP_WAIT(0);
            __syncthreads();
            const uint32_t base = sb + (s & 3) * STAGE_HALVES * 2;
            uint32_t ah[2][4], al[2][4], bh[4][4], bl[4][4];
            #pragma unroll
            for (int mf = 0; mf < 2; mf++) {
                uint32_t ra = base + ((wm*32 + mf*16 + lr) * GLD + lh*8) * 2;
                ldm_x4(ah[mf], ra + T_A_HI*2);
                ldm_x4(al[mf], ra + T_A_LO*2);
            }
            #pragma unroll
            for (int nb = 0; nb < 4; nb++) {
                uint32_t rb = base + ((wn*64 + nb*16 + lr) * GLD + lh*8) * 2;
                ldm_x4(bh[nb], rb + T_B_HI*2);
                ldm_x4(bl[nb], rb + T_B_LO*2);
            }
            #pragma unroll
            for (int mf = 0; mf < 2; mf++)
                #pragma unroll
                for (int nb = 0; nb < 4; nb++)
                    #pragma unroll
                    for (int sub = 0; sub < 2; sub++) {
                        float* c = acc[mf][nb*2 + sub];
                        mma_bf16(c, ah[mf], bh[nb][sub], bh[nb][sub+2]);
                        mma_bf16(c, ah[mf], bl[nb][sub], bl[nb][sub+2]);
                        mma_bf16(c, al[mf], bh[nb][sub], bh[nb][sub+2]);
                    }
            __syncthreads();
        }
    }
};

// ---- fused Q/K/V projection: grid (16, 32, 3), z: 0=Q 1=K 2=V ----------------------
__global__ void __launch_bounds__(256, 2)
qkv_mma(const float* __restrict__ bq, const float* __restrict__ bk,
        const float* __restrict__ bv)
{
    extern __shared__ __nv_bfloat16 smem[];
    const int m0 = blockIdx.y * 128;
    const int n0 = blockIdx.x * 128;
    const int z  = blockIdx.z;

    GemmCore core;
    core.init(smem_u32(smem), m0, n0, g_xhi, g_xlo, g_whi[z], g_wlo[z]);

    float acc[2][8][4];
    #pragma unroll
    for (int i = 0; i < 2; i++)
        #pragma unroll
        for (int j = 0; j < 8; j++)
            #pragma unroll
            for (int k = 0; k < 4; k++) acc[i][j][k] = 0.f;

    core.run(acc);

    const float* bias = (z == 0) ? bq : (z == 1) ? bk : bv;
    __nv_bfloat16* dhi = (z == 0) ? g_qhi : (z == 1) ? g_khi : g_vhi;
    __nv_bfloat16* dlo = (z == 0) ? g_qlo : (z == 1) ? g_klo : g_vlo;
    const bool do_rope = (z != 2);
    const float sc = (z == 0) ? QK_SCALE : 1.0f;

    const int g = core.lane >> 2, t = core.lane & 3;
    #pragma unroll
    for (int mf = 0; mf < 2; mf++) {
        const int r0 = m0 + core.wm*32 + mf*16 + g;
        const int r1 = r0 + 8;
        const int bb0 = r0 >> 11, pos0 = r0 & 2047;
        const int bb1 = r1 >> 11, pos1 = r1 & 2047;
        #pragma unroll
        for (int nf = 0; nf < 8; nf++) {
            const int col = n0 + core.wn*64 + nf*8 + 2*t;
            float b0 = bias[col], b1 = bias[col + 1];
            float v00 = acc[mf][nf][0] + b0, v01 = acc[mf][nf][1] + b1;
            float v10 = acc[mf][nf][2] + b0, v11 = acc[mf][nf][3] + b1;
            if (do_rope) {
                const int p = (col & 127) >> 1;
                float cs0 = g_cos[pos0*64 + p], sn0 = g_sin[pos0*64 + p];
                float cs1 = g_cos[pos1*64 + p], sn1 = g_sin[pos1*64 + p];
                float x1 = v00, x2 = v01;
                v00 = (x1*cs0 - x2*sn0) * sc;  v01 = (x1*sn0 + x2*cs0) * sc;
                x1 = v10; x2 = v11;
                v10 = (x1*cs1 - x2*sn1) * sc;  v11 = (x1*sn1 + x2*cs1) * sc;
            }
            const int h = col >> 7, d = col & 127;
            size_t base0 = (((size_t)(bb0*NHEADS + h) * SEQLEN + pos0) * DHEAD + d);
            size_t base1 = (((size_t)(bb1*NHEADS + h) * SEQLEN + pos1) * DHEAD + d);
            __nv_bfloat16 h00 = __float2bfloat16(v00), h01 = __float2bfloat16(v01);
            __nv_bfloat16 h10 = __float2bfloat16(v10), h11 = __float2bfloat16(v11);
            __nv_bfloat162 hp0; hp0.x = h00; hp0.y = h01;
            __nv_bfloat162 hp1; hp1.x = h10; hp1.y = h11;
            *(__nv_bfloat162*)(dhi + base0) = hp0;
            *(__nv_bfloat162*)(dhi + base1) = hp1;
            __nv_bfloat162 lp0, lp1;
            lp0.x = __float2bfloat16(v00 - __bfloat162float(h00));
            lp0.y = __float2bfloat16(v01 - __bfloat162float(h01));
            lp1.x = __float2bfloat16(v10 - __bfloat162float(h10));
            lp1.y = __float2bfloat16(v11 - __bfloat162float(h11));
            *(__nv_bfloat162*)(dlo + base0) = lp0;
            *(__nv_bfloat162*)(dlo + base1) = lp1;
        }
    }
}

// ---- output projection -------------------------------------------------------------
__global__ void __launch_bounds__(256, 2)
out_mma(const float* __restrict__ bias, float* __restrict__ outp)
{
    extern __shared__ __nv_bfloat16 smem[];
    const int m0 = blockIdx.y * 128;
    const int n0 = blockIdx.x * 128;

    GemmCore core;
    core.init(smem_u32(smem), m0, n0, g_ahi, g_alo, g_whi[3], g_wlo[3]);

    float acc[2][8][4];
    #pragma unroll
    for (int i = 0; i < 2; i++)
        #pragma unroll
        for (int j = 0; j < 8; j++)
            #pragma unroll
            for (int k = 0; k < 4; k++) acc[i][j][k] = 0.f;

    core.run(acc);

    const int g = core.lane >> 2, t = core.lane & 3;
    #pragma unroll
    for (int mf = 0; mf < 2; mf++) {
        const int r0 = m0 + core.wm*32 + mf*16 + g;
        const int r1 = r0 + 8;
        #pragma unroll
        for (int nf = 0; nf < 8; nf++) {
            const int col = n0 + core.wn*64 + nf*8 + 2*t;
            float b0 = bias[col], b1 = bias[col + 1];
            *(float2*)(outp + (size_t)r0 * 2048 + col) =
                make_float2(acc[mf][nf][0] + b0, acc[mf][nf][1] + b1);
            *(float2*)(outp + (size_t)r1 * 2048 + col) =
                make_float2(acc[mf][nf][2] + b0, acc[mf][nf][3] + b1);
        }
    }
}

// ---------------- tensor-core flash attention (3-stage KV pipeline) ----------------
#define KVLD    136
#define TILE_H  (64*KVLD)
#define BUF_H   (4*TILE_H)
#define QLO_OFF (128*KVLD)
#define SM_ATTN_BYTES (3*BUF_H*2)            // 208896 B

__global__ void __launch_bounds__(256, 1)
attn_mma()
{
    extern __shared__ __nv_bfloat16 smn[];
    const uint32_t sb = smem_u32(smn);
    const int tid = threadIdx.x, lane = tid & 31, w = tid >> 5;
    const int bh = blockIdx.y;
    const int qt = 15 - blockIdx.x;
    const int q0 = qt * 128;

    const size_t qoff = ((size_t)bh * SEQLEN + q0) * DHEAD;
    const __nv_bfloat16* Qhg = g_qhi + qoff;
    const __nv_bfloat16* Qlg = g_qlo + qoff;

    for (int idx = tid; idx < 2048; idx += 256) {
        int row = idx >> 4, c = idx & 15;
        uint32_t off = (uint32_t)(row * KVLD + c * 8) * 2;
        cp16(sb + off,             Qhg + row * 128 + c * 8);
        cp16(sb + QLO_OFF*2 + off, Qlg + row * 128 + c * 8);
    }
    CP_COMMIT(); CP_WAIT(0);
    __syncthreads();

    uint32_t qh[8][4], ql[8][4];
    const int lr = lane & 15, lhb = lane >> 4;
    #pragma unroll
    for (int kk = 0; kk < 8; kk++) {
        uint32_t ra = sb + (uint32_t)((w*16 + lr) * KVLD + kk*16 + lhb*8) * 2;
        ldm_x4(qh[kk], ra);
        ldm_x4(ql[kk], ra + QLO_OFF*2);
    }
    __syncthreads();

    auto load_kv = [&](int jt, int buf) {
        const size_t koff = ((size_t)bh * SEQLEN + jt * 64) * DHEAD;
        const __nv_bfloat16* Kh = g_khi + koff;
        const __nv_bfloat16* Kl = g_klo + koff;
        const __nv_bfloat16* Vh = g_vhi + koff;
        const __nv_bfloat16* Vl = g_vlo + koff;
        const uint32_t base = sb + buf * BUF_H * 2;
        for (int idx = tid; idx < 1024; idx += 256) {
            int row = idx >> 4, c = idx & 15;
            uint32_t off = (uint32_t)(row * KVLD + c * 8) * 2;
            int so = row * 128 + c * 8;
            cp16(base + off,              Kh + so);
            cp16(base + TILE_H*2 + off,   Kl + so);
            cp16(base + 2*TILE_H*2 + off, Vh + so);
            cp16(base + 3*TILE_H*2 + off, Vl + so);
        }
    };

    float m_[2] = {-INFINITY, -INFINITY};
    float l_[2] = {0.f, 0.f};
    float o[16][4];
    #pragma unroll
    for (int i = 0; i < 16; i++)
        #pragma unroll
        for (int j = 0; j < 4; j++) o[i][j] = 0.f;

    const int g  = lane >> 2, t2 = (lane & 3) * 2;
    const int wrow0 = q0 + w * 16;
    const int row0  = wrow0 + g;

    const int ntiles = 2 * qt + 2;
    load_kv(0, 0); CP_COMMIT();
    if (1 < ntiles) { load_kv(1, 1); CP_COMMIT(); }
    if (2 < ntiles) { load_kv(2, 2); CP_COMMIT(); }

    for (int jt = 0; jt < ntiles; jt++) {
        const int buf = jt % 3;
        const int kv0 = jt * 64;
        const int rem = ntiles - 1 - jt;
        if      (rem >= 2) CP_WAIT(2);
        else if (rem == 1) CP_WAIT(1);
        else               CP_WAIT(0);
        __syncthreads();

        const bool skip = (wrow0 + 15 < kv0);
        if (!skip) {
            const uint32_t base = sb + buf * BUF_H * 2;

            float s[8][4];
            #pragma unroll
            for (int i = 0; i < 8; i++)
                #pragma unroll
                for (int j = 0; j < 4; j++) s[i][j] = 0.f;

            #pragma unroll
            for (int kk = 0; kk < 8; kk++) {
                #pragma unroll
                for (int nb = 0; nb < 4; nb++) {
                    uint32_t kh4[4], kl4[4];
                    uint32_t rb = base + (uint32_t)((nb*16 + lr) * KVLD + kk*16 + lhb*8) * 2;
                    ldm_x4(kh4, rb);
                    ldm_x4(kl4, rb + TILE_H*2);
                    #pragma unroll
                    for (int sub = 0; sub < 2; sub++) {
                        float* c = s[nb*2 + sub];
                        mma_bf16(c, qh[kk], kh4[sub], kh4[sub+2]);
                        mma_bf16(c, qh[kk], kl4[sub], kl4[sub+2]);
                        mma_bf16(c, ql[kk], kh4[sub], kh4[sub+2]);
                    }
                }
            }

            if (kv0 + 63 > wrow0) {
                #pragma unroll
                for (int nf = 0; nf < 8; nf++) {
                    int c0 = kv0 + nf*8 + t2;
                    if (c0     > row0)     s[nf][0] = -1e30f;
                    if (c0 + 1 > row0)     s[nf][1] = -1e30f;
                    if (c0     > row0 + 8) s[nf][2] = -1e30f;
                    if (c0 + 1 > row0 + 8) s[nf][3] = -1e30f;
                }
            }

            float mx0 = -INFINITY, mx1 = -INFINITY;
            #pragma unroll
            for (int nf = 0; nf < 8; nf++) {
                mx0 = fmaxf(mx0, fmaxf(s[nf][0], s[nf][1]));
                mx1 = fmaxf(mx1, fmaxf(s[nf][2], s[nf][3]));
            }
            mx0 = fmaxf(mx0, __shfl_xor_sync(0xffffffffu, mx0, 1));
            mx0 = fmaxf(mx0, __shfl_xor_sync(0xffffffffu, mx0, 2));
            mx1 = fmaxf(mx1, __shfl_xor_sync(0xffffffffu, mx1, 1));
            mx1 = fmaxf(mx1, __shfl_xor_sync(0xffffffffu, mx1, 2));
            float mn0 = fmaxf(m_[0], mx0), mn1 = fmaxf(m_[1], mx1);
            float f0 = __expf(m_[0] - mn0), f1 = __expf(m_[1] - mn1);
            m_[0] = mn0; m_[1] = mn1;

            float sum0 = 0.f, sum1 = 0.f;
            #pragma unroll
            for (int nf = 0; nf < 8; nf++) {
                s[nf][0] = __expf(s[nf][0] - mn0); sum0 += s[nf][0];
                s[nf][1] = __expf(s[nf][1] - mn0); sum0 += s[nf][1];
                s[nf][2] = __expf(s[nf][2] - mn1); sum1 += s[nf][2];
                s[nf][3] = __expf(s[nf][3] - mn1); sum1 += s[nf][3];
            }
            sum0 += __shfl_xor_sync(0xffffffffu, sum0, 1);
            sum0 += __shfl_xor_sync(0xffffffffu, sum0, 2);
            sum1 += __shfl_xor_sync(0xffffffffu, sum1, 1);
            sum1 += __shfl_xor_sync(0xffffffffu, sum1, 2);
            l_[0] = l_[0] * f0 + sum0;
            l_[1] = l_[1] * f1 + sum1;

            #pragma unroll
            for (int nf = 0; nf < 16; nf++) {
                o[nf][0] *= f0; o[nf][1] *= f0;
                o[nf][2] *= f1; o[nf][3] *= f1;
            }

            uint32_t ph[4][4], pl[4][4];
            #pragma unroll
            for (int kf = 0; kf < 4; kf++) {
                #pragma unroll
                for (int j = 0; j < 4; j++) {
                    int nf = 2*kf + (j >> 1);
                    int c0 = (j & 1) * 2;
                    float p0 = s[nf][c0], p1 = s[nf][c0 + 1];
                    __nv_bfloat16 b0 = __float2bfloat16(p0), b1 = __float2bfloat16(p1);
                    __nv_bfloat162 hb; hb.x = b0; hb.y = b1;
                    ph[kf][j] = *(uint32_t*)&hb;
                    pl[kf][j] = packbf2(p0 - __bfloat162float(b0), p1 - __bfloat162float(b1));
                }
            }

            const uint32_t vbase = base + 2*TILE_H*2;
            const int matv = lane >> 3, jv = lane & 7;
            #pragma unroll
            for (int kf = 0; kf < 4; kf++) {
                #pragma unroll
                for (int ng = 0; ng < 8; ng++) {
                    uint32_t vh4[4], vl4[4];
                    uint32_t va = vbase + (uint32_t)((kf*16 + jv + ((matv & 1) << 3)) * KVLD
                                                    + ng*16 + ((matv >> 1) << 3)) * 2;
                    ldm_x4_t(vh4, va);
                    ldm_x4_t(vl4, va + TILE_H*2);
                    #pragma unroll
                    for (int sub = 0; sub < 2; sub++) {
                        float* c = o[ng*2 + sub];
                        mma_bf16(c, ph[kf], vh4[sub*2], vh4[sub*2+1]);
                        mma_bf16(c, ph[kf], vl4[sub*2], vl4[sub*2+1]);
                        mma_bf16(c, pl[kf], vh4[sub*2], vh4[sub*2+1]);
                    }
                }
            }
        }
        __syncthreads();
        if (jt + 3 < ntiles) { load_kv(jt + 3, (jt + 3) % 3); CP_COMMIT(); }
    }

    const float inv0 = 1.f / l_[0];
    const float inv1 = 1.f / l_[1];
    const int bb = bh >> 4, h = bh & 15;
    const size_t rA0 = (size_t)(bb * SEQLEN + row0) * D_MODEL + h * DHEAD;
    const size_t rA1 = rA0 + 8 * D_MODEL;
    #pragma unroll
    for (int nf = 0; nf < 16; nf++) {
        int d = nf*8 + t2;
        float v00 = o[nf][0]*inv0, v01 = o[nf][1]*inv0;
        float v10 = o[nf][2]*inv1, v11 = o[nf][3]*inv1;
        __nv_bfloat16 h00 = __float2bfloat16(v00), h01 = __float2bfloat16(v01);
        __nv_bfloat16 h10 = __float2bfloat16(v10), h11 = __float2bfloat16(v11);
        __nv_bfloat162 hp0; hp0.x = h00; hp0.y = h01;
        __nv_bfloat162 hp1; hp1.x = h10; hp1.y = h11;
        *(__nv_bfloat162*)(g_ahi + rA0 + d) = hp0;
        *(__nv_bfloat162*)(g_ahi + rA1 + d) = hp1;
        __nv_bfloat162 lp0, lp1;
        lp0.x = __float2bfloat16(v00 - __bfloat162float(h00));
        lp0.y = __float2bfloat16(v01 - __bfloat162float(h01));
        lp1.x = __float2bfloat16(v10 - __bfloat162float(h10));
        lp1.y = __float2bfloat16(v11 - __bfloat162float(h11));
        *(__nv_bfloat162*)(g_alo + rA0 + d) = lp0;
        *(__nv_bfloat162*)(g_alo + rA1 + d) = lp1;
    }
}

// ---------------- launch -----------------------------------------------------------
extern "C" void kernel_launch(void* const* d_in, const int* in_sizes, int n_in,
                              void* d_out, int out_size)
{
    const float* x  = (const float*)d_in[0];
    const float* Wq = (const float*)d_in[1];
    const float* bq = (const float*)d_in[2];
    const float* Wk = (const float*)d_in[3];
    const float* bk = (const float*)d_in[4];
    const float* Wv = (const float*)d_in[5];
    const float* bv = (const float*)d_in[6];
    const float* Wo = (const float*)d_in[7];
    const float* bo = (const float*)d_in[8];
    float* out = (float*)d_out;

    cudaFuncSetAttribute(attn_mma, cudaFuncAttributeMaxDynamicSharedMemorySize, SM_ATTN_BYTES);
    cudaFuncSetAttribute(qkv_mma,  cudaFuncAttributeMaxDynamicSharedMemorySize, SMEM_GEMM_BYTES);
    cudaFuncSetAttribute(out_mma,  cudaFuncAttributeMaxDynamicSharedMemorySize, SMEM_GEMM_BYTES);

    rope_table_kernel<<<512, 256>>>();

    const int NX = MROWS * D_MODEL;
    const int NW = D_MODEL * D_MODEL;
    split_x_kernel<<<NX/256, 256>>>(x);
    split_w_kernel<<<dim3(NW/256, 4), 256>>>(Wq, Wk, Wv, Wo);

    qkv_mma<<<dim3(16, 32, 3), 256, SMEM_GEMM_BYTES>>>(bq, bk, bv);

    attn_mma<<<dim3(16, 32), 256, SM_ATTN_BYTES>>>();

    out_mma<<<dim3(16, 32), 256, SMEM_GEMM_BYTES>>>(bo, out);
}

// round 9
// speedup vs baseline: 2.8740x; 1.0092x over previous
#include <cuda_runtime.h>
#include <cuda_bf16.h>
#include <math.h>
#include <stdint.h>

#define D_MODEL 2048
#define NHEADS  16
#define DHEAD   128
#define SEQLEN  2048
#define BATCH   2
#define MROWS   (BATCH*SEQLEN)   // 4096
#define QK_SCALE 0.08838834764831845f   // 1/sqrt(128)

// ---------------- scratch (device globals; no allocation allowed) ----------------
__device__ float g_cos[SEQLEN*(DHEAD/2)];
__device__ float g_sin[SEQLEN*(DHEAD/2)];

__device__ __nv_bfloat16 g_xhi[MROWS*D_MODEL];
__device__ __nv_bfloat16 g_xlo[MROWS*D_MODEL];
__device__ __nv_bfloat16 g_whi[4][D_MODEL*D_MODEL];   // 0=Wq 1=Wk 2=Wv 3=Wo
__device__ __nv_bfloat16 g_wlo[4][D_MODEL*D_MODEL];
__device__ __nv_bfloat16 g_ahi[MROWS*D_MODEL];        // attention out, x-layout
__device__ __nv_bfloat16 g_alo[MROWS*D_MODEL];
__device__ __nv_bfloat16 g_qhi[BATCH*NHEADS*SEQLEN*DHEAD];
__device__ __nv_bfloat16 g_qlo[BATCH*NHEADS*SEQLEN*DHEAD];
__device__ __nv_bfloat16 g_khi[BATCH*NHEADS*SEQLEN*DHEAD];
__device__ __nv_bfloat16 g_klo[BATCH*NHEADS*SEQLEN*DHEAD];
__device__ __nv_bfloat16 g_vhi[BATCH*NHEADS*SEQLEN*DHEAD];
__device__ __nv_bfloat16 g_vlo[BATCH*NHEADS*SEQLEN*DHEAD];

// ---------------- PTX helpers (sm_80-level only) -----------------------------------
__device__ __forceinline__ uint32_t smem_u32(const void* p) {
    uint32_t a;
    asm("{ .reg .u64 t; cvta.to.shared.u64 t, %1; cvt.u32.u64 %0, t; }" : "=r"(a) : "l"(p));
    return a;
}
__device__ __forceinline__ void cp16(uint32_t dst, const void* src) {
    asm volatile("cp.async.cg.shared.global [%0], [%1], 16;" :: "r"(dst), "l"(src));
}
#define CP_COMMIT() asm volatile("cp.async.commit_group;" ::: "memory")
#define CP_WAIT(n)  asm volatile("cp.async.wait_group %0;" :: "n"(n) : "memory")

__device__ __forceinline__ void ldm_x4(uint32_t* r, uint32_t addr) {
    asm volatile("ldmatrix.sync.aligned.m8n8.x4.shared.b16 {%0,%1,%2,%3}, [%4];"
                 : "=r"(r[0]), "=r"(r[1]), "=r"(r[2]), "=r"(r[3]) : "r"(addr));
}
__device__ __forceinline__ void ldm_x4_t(uint32_t* r, uint32_t addr) {
    asm volatile("ldmatrix.sync.aligned.m8n8.x4.trans.shared.b16 {%0,%1,%2,%3}, [%4];"
                 : "=r"(r[0]), "=r"(r[1]), "=r"(r[2]), "=r"(r[3]) : "r"(addr));
}
__device__ __forceinline__ void mma_bf16(float* c, const uint32_t* a, uint32_t b0, uint32_t b1) {
    asm volatile("mma.sync.aligned.m16n8k16.row.col.f32.bf16.bf16.f32 "
                 "{%0,%1,%2,%3}, {%4,%5,%6,%7}, {%8,%9}, {%0,%1,%2,%3};"
                 : "+f"(c[0]), "+f"(c[1]), "+f"(c[2]), "+f"(c[3])
                 : "r"(a[0]), "r"(a[1]), "r"(a[2]), "r"(a[3]), "r"(b0), "r"(b1));
}
__device__ __forceinline__ uint32_t packbf2(float lo, float hi) {
    uint32_t r;
    asm("cvt.rn.bf16x2.f32 %0, %1, %2;" : "=r"(r) : "f"(hi), "f"(lo));
    return r;
}

// ---------------- RoPE tables ------------------------------------------------------
__global__ void rope_table_kernel() {
    int idx = blockIdx.x * blockDim.x + threadIdx.x;
    int pos = idx >> 6;
    int p   = idx & 63;
    double freq = exp(-((double)(2 * p) / 128.0) * log(10000.0));
    double ang  = (double)pos * freq;
    g_cos[idx] = (float)cos(ang);
    g_sin[idx] = (float)sin(ang);
}

// ---------------- hi/lo bf16 split kernels -----------------------------------------
__global__ void split_x_kernel(const float* __restrict__ src) {
    int i = blockIdx.x * 256 + threadIdx.x;
    float v = src[i];
    __nv_bfloat16 h = __float2bfloat16(v);
    g_xhi[i] = h;
    g_xlo[i] = __float2bfloat16(v - __bfloat162float(h));
}
__global__ void split_w_kernel(const float* __restrict__ w0, const float* __restrict__ w1,
                               const float* __restrict__ w2, const float* __restrict__ w3) {
    int i = blockIdx.x * 256 + threadIdx.x;
    int wsel = blockIdx.y;
    const float* s = (wsel == 0) ? w0 : (wsel == 1) ? w1 : (wsel == 2) ? w2 : w3;
    float v = s[i];
    __nv_bfloat16 h = __float2bfloat16(v);
    g_whi[wsel][i] = h;
    g_wlo[wsel][i] = __float2bfloat16(v - __bfloat162float(h));
}

// ---------------- mma.sync split-bf16 GEMM core (unchanged from R8) ----------------
#define GLD 24
#define T_A_HI 0
#define T_A_LO (128*GLD)
#define T_B_HI (2*128*GLD)
#define T_B_LO (3*128*GLD)
#define STAGE_HALVES (4*128*GLD)
#define SMEM_GEMM_BYTES (4*STAGE_HALVES*2)

struct GemmCore {
    uint32_t sb;
    int lane, wm, wn, lrow, lc, lr, lh;
    const __nv_bfloat16 *pAh, *pAl, *pBh, *pBl;

    __device__ __forceinline__ void init(uint32_t sb_, int m0, int n0,
                                         const __nv_bfloat16* Ahi, const __nv_bfloat16* Alo,
                                         const __nv_bfloat16* Bhi, const __nv_bfloat16* Blo) {
        sb = sb_;
        int tid = threadIdx.x;
        lane = tid & 31;
        int warp = tid >> 5;
        wm = warp & 3; wn = warp >> 2;
        lrow = tid & 127; lc = tid >> 7;
        lr = lane & 15; lh = lane >> 4;
        pAh = Ahi + (size_t)(m0 + lrow) * 2048;
        pAl = Alo + (size_t)(m0 + lrow) * 2048;
        pBh = Bhi + (size_t)(n0 + lrow) * 2048;
        pBl = Blo + (size_t)(n0 + lrow) * 2048;
    }
    __device__ __forceinline__ void load_stage(int s, int buf) {
        const int ks = s * 16 + lc * 8;
        const uint32_t base = sb + buf * STAGE_HALVES * 2;
        const uint32_t off = (lrow * GLD + lc * 8) * 2;
        cp16(base + T_A_HI*2 + off, pAh + ks);
        cp16(base + T_A_LO*2 + off, pAl + ks);
        cp16(base + T_B_HI*2 + off, pBh + ks);
        cp16(base + T_B_LO*2 + off, pBl + ks);
    }
    __device__ __forceinline__ void run(float acc[2][8][4]) {
        load_stage(0, 0); CP_COMMIT();
        load_stage(1, 1); CP_COMMIT();
        load_stage(2, 2); CP_COMMIT();
        for (int s = 0; s < 128; s++) {
            if (s + 3 < 128) { load_stage(s + 3, (s + 3) & 3); CP_COMMIT(); }
            if      (s < 125)  CP_WAIT(3);
            else if (s == 125) CP_WAIT(2);
            else if (s == 126) CP_WAIT(1);
            else               CP_WAIT(0);
            __syncthreads();
            const uint32_t base = sb + (s & 3) * STAGE_HALVES * 2;
            uint32_t ah[2][4], al[2][4], bh[4][4], bl[4][4];
            #pragma unroll
            for (int mf = 0; mf < 2; mf++) {
                uint32_t ra = base + ((wm*32 + mf*16 + lr) * GLD + lh*8) * 2;
                ldm_x4(ah[mf], ra + T_A_HI*2);
                ldm_x4(al[mf], ra + T_A_LO*2);
            }
            #pragma unroll
            for (int nb = 0; nb < 4; nb++) {
                uint32_t rb = base + ((wn*64 + nb*16 + lr) * GLD + lh*8) * 2;
                ldm_x4(bh[nb], rb + T_B_HI*2);
                ldm_x4(bl[nb], rb + T_B_LO*2);
            }
            #pragma unroll
            for (int mf = 0; mf < 2; mf++)
                #pragma unroll
                for (int nb = 0; nb < 4; nb++)
                    #pragma unroll
                    for (int sub = 0; sub < 2; sub++) {
                        float* c = acc[mf][nb*2 + sub];
                        mma_bf16(c, ah[mf], bh[nb][sub], bh[nb][sub+2]);
                        mma_bf16(c, ah[mf], bl[nb][sub], bl[nb][sub+2]);
                        mma_bf16(c, al[mf], bh[nb][sub], bh[nb][sub+2]);
                    }
            __syncthreads();
        }
    }
};

__global__ void __launch_bounds__(256, 2)
qkv_mma(const float* __restrict__ bq, const float* __restrict__ bk,
        const float* __restrict__ bv)
{
    extern __shared__ __nv_bfloat16 smem[];
    const int m0 = blockIdx.y * 128;
    const int n0 = blockIdx.x * 128;
    const int z  = blockIdx.z;

    GemmCore core;
    core.init(smem_u32(smem), m0, n0, g_xhi, g_xlo, g_whi[z], g_wlo[z]);

    float acc[2][8][4];
    #pragma unroll
    for (int i = 0; i < 2; i++)
        #pragma unroll
        for (int j = 0; j < 8; j++)
            #pragma unroll
            for (int k = 0; k < 4; k++) acc[i][j][k] = 0.f;

    core.run(acc);

    const float* bias = (z == 0) ? bq : (z == 1) ? bk : bv;
    __nv_bfloat16* dhi = (z == 0) ? g_qhi : (z == 1) ? g_khi : g_vhi;
    __nv_bfloat16* dlo = (z == 0) ? g_qlo : (z == 1) ? g_klo : g_vlo;
    const bool do_rope = (z != 2);
    const float sc = (z == 0) ? QK_SCALE : 1.0f;

    const int g = core.lane >> 2, t = core.lane & 3;
    #pragma unroll
    for (int mf = 0; mf < 2; mf++) {
        const int r0 = m0 + core.wm*32 + mf*16 + g;
        const int r1 = r0 + 8;
        const int bb0 = r0 >> 11, pos0 = r0 & 2047;
        const int bb1 = r1 >> 11, pos1 = r1 & 2047;
        #pragma unroll
        for (int nf = 0; nf < 8; nf++) {
            const int col = n0 + core.wn*64 + nf*8 + 2*t;
            float b0 = bias[col], b1 = bias[col + 1];
            float v00 = acc[mf][nf][0] + b0, v01 = acc[mf][nf][1] + b1;
            float v10 = acc[mf][nf][2] + b0, v11 = acc[mf][nf][3] + b1;
            if (do_rope) {
                const int p = (col & 127) >> 1;
                float cs0 = g_cos[pos0*64 + p], sn0 = g_sin[pos0*64 + p];
                float cs1 = g_cos[pos1*64 + p], sn1 = g_sin[pos1*64 + p];
                float x1 = v00, x2 = v01;
                v00 = (x1*cs0 - x2*sn0) * sc;  v01 = (x1*sn0 + x2*cs0) * sc;
                x1 = v10; x2 = v11;
                v10 = (x1*cs1 - x2*sn1) * sc;  v11 = (x1*sn1 + x2*cs1) * sc;
            }
            const int h = col >> 7, d = col & 127;
            size_t base0 = (((size_t)(bb0*NHEADS + h) * SEQLEN + pos0) * DHEAD + d);
            size_t base1 = (((size_t)(bb1*NHEADS + h) * SEQLEN + pos1) * DHEAD + d);
            __nv_bfloat16 h00 = __float2bfloat16(v00), h01 = __float2bfloat16(v01);
            __nv_bfloat16 h10 = __float2bfloat16(v10), h11 = __float2bfloat16(v11);
            __nv_bfloat162 hp0; hp0.x = h00; hp0.y = h01;
            __nv_bfloat162 hp1; hp1.x = h10; hp1.y = h11;
            *(__nv_bfloat162*)(dhi + base0) = hp0;
            *(__nv_bfloat162*)(dhi + base1) = hp1;
            __nv_bfloat162 lp0, lp1;
            lp0.x = __float2bfloat16(v00 - __bfloat162float(h00));
            lp0.y = __float2bfloat16(v01 - __bfloat162float(h01));
            lp1.x = __float2bfloat16(v10 - __bfloat162float(h10));
            lp1.y = __float2bfloat16(v11 - __bfloat162float(h11));
            *(__nv_bfloat162*)(dlo + base0) = lp0;
            *(__nv_bfloat162*)(dlo + base1) = lp1;
        }
    }
}

__global__ void __launch_bounds__(256, 2)
out_mma(const float* __restrict__ bias, float* __restrict__ outp)
{
    extern __shared__ __nv_bfloat16 smem[];
    const int m0 = blockIdx.y * 128;
    const int n0 = blockIdx.x * 128;

    GemmCore core;
    core.init(smem_u32(smem), m0, n0, g_ahi, g_alo, g_whi[3], g_wlo[3]);

    float acc[2][8][4];
    #pragma unroll
    for (int i = 0; i < 2; i++)
        #pragma unroll
        for (int j = 0; j < 8; j++)
            #pragma unroll
            for (int k = 0; k < 4; k++) acc[i][j][k] = 0.f;

    core.run(acc);

    const int g = core.lane >> 2, t = core.lane & 3;
    #pragma unroll
    for (int mf = 0; mf < 2; mf++) {
        const int r0 = m0 + core.wm*32 + mf*16 + g;
        const int r1 = r0 + 8;
        #pragma unroll
        for (int nf = 0; nf < 8; nf++) {
            const int col = n0 + core.wn*64 + nf*8 + 2*t;
            float b0 = bias[col], b1 = bias[col + 1];
            *(float2*)(outp + (size_t)r0 * 2048 + col) =
                make_float2(acc[mf][nf][0] + b0, acc[mf][nf][1] + b1);
            *(float2*)(outp + (size_t)r1 * 2048 + col) =
                make_float2(acc[mf][nf][2] + b0, acc[mf][nf][3] + b1);
        }
    }
}

// ---------------- tensor-core flash attention, occupancy 2 -------------------------
// 128 threads (4 warps), BQ=64 (16 rows/warp), BKV=64.
// K double-buffered (hi/lo), V single-buffered. grid (32 q-tiles, 32 bh).
#define AKVLD 136
#define A_SUB 8704                       // 64*136 halves per sub-tile
#define A_KH(b) ((b)*2*A_SUB)            // Khi of buffer b
#define A_KL(b) ((b)*2*A_SUB + A_SUB)    // Klo of buffer b
#define A_VH   (4*A_SUB)
#define A_VL   (5*A_SUB)
#define SM_ATTN_BYTES (6*A_SUB*2)        // 104448 B -> occupancy 2

__global__ void __launch_bounds__(128, 2)
attn_mma()
{
    extern __shared__ __nv_bfloat16 smn[];
    const uint32_t sb = smem_u32(smn);
    const int tid = threadIdx.x, lane = tid & 31, w = tid >> 5;
    const int bh = blockIdx.y;
    const int qt = 31 - blockIdx.x;          // heavy tiles first
    const int q0 = qt * 64;

    // ---- stage Q (64x128 hi+lo) into K-buffer area, build A-frags ----
    const size_t qoff = ((size_t)bh * SEQLEN + q0) * DHEAD;
    for (int idx = tid; idx < 1024; idx += 128) {
        int row = idx >> 4, c = idx & 15;
        uint32_t off = (uint32_t)(row * AKVLD + c * 8) * 2;
        cp16(sb + A_KH(0)*2 + off, g_qhi + qoff + row * 128 + c * 8);
        cp16(sb + A_KL(0)*2 + off, g_qlo + qoff + row * 128 + c * 8);
    }
    CP_COMMIT(); CP_WAIT(0);
    __syncthreads();

    uint32_t qh[8][4], ql[8][4];
    const int lr = lane & 15, lhb = lane >> 4;
    #pragma unroll
    for (int kk = 0; kk < 8; kk++) {
        uint32_t ra = sb + (uint32_t)((w*16 + lr) * AKVLD + kk*16 + lhb*8) * 2;
        ldm_x4(qh[kk], ra + A_KH(0)*2);
        ldm_x4(ql[kk], ra + A_KL(0)*2);
    }
    __syncthreads();     // Q consumed; K buffer 0 reusable

    auto load_K = [&](int jt, int buf) {
        const size_t koff = ((size_t)bh * SEQLEN + jt * 64) * DHEAD;
        for (int idx = tid; idx < 1024; idx += 128) {
            int row = idx >> 4, c = idx & 15;
            uint32_t off = (uint32_t)(row * AKVLD + c * 8) * 2;
            int so = row * 128 + c * 8;
            cp16(sb + A_KH(buf)*2 + off, g_khi + koff + so);
            cp16(sb + A_KL(buf)*2 + off, g_klo + koff + so);
        }
    };
    auto load_V = [&](int jt) {
        const size_t koff = ((size_t)bh * SEQLEN + jt * 64) * DHEAD;
        for (int idx = tid; idx < 1024; idx += 128) {
            int row = idx >> 4, c = idx & 15;
            uint32_t off = (uint32_t)(row * AKVLD + c * 8) * 2;
            int so = row * 128 + c * 8;
            cp16(sb + A_VH*2 + off, g_vhi + koff + so);
            cp16(sb + A_VL*2 + off, g_vlo + koff + so);
        }
    };

    float m_[2] = {-INFINITY, -INFINITY};
    float l_[2] = {0.f, 0.f};
    float o[16][4];
    #pragma unroll
    for (int i = 0; i < 16; i++)
        #pragma unroll
        for (int j = 0; j < 4; j++) o[i][j] = 0.f;

    const int g  = lane >> 2, t2 = (lane & 3) * 2;
    const int wrow0 = q0 + w * 16;
    const int row0  = wrow0 + g;

    const int ntiles = qt + 1;
    load_K(0, 0); CP_COMMIT();           // group {K0}
    load_V(0);    CP_COMMIT();           // group {V0}

    for (int jt = 0; jt < ntiles; jt++) {
        const int kbuf = jt & 1;
        const int kv0 = jt * 64;
        const bool more = (jt + 1 < ntiles);

        if (more) { load_K(jt + 1, kbuf ^ 1); CP_COMMIT(); }   // overlaps S+softmax+PV
        if (more) CP_WAIT(2); else CP_WAIT(1);                 // K(jt) ready
        __syncthreads();

        const uint32_t kb = sb + A_KH(kbuf) * 2;

        // ---- S = Q K^T (3-term split) ----
        float s[8][4];
        #pragma unroll
        for (int i = 0; i < 8; i++)
            #pragma unroll
            for (int j = 0; j < 4; j++) s[i][j] = 0.f;

        #pragma unroll
        for (int kk = 0; kk < 8; kk++) {
            #pragma unroll
            for (int nb = 0; nb < 4; nb++) {
                uint32_t kh4[4], kl4[4];
                uint32_t rb = kb + (uint32_t)((nb*16 + lr) * AKVLD + kk*16 + lhb*8) * 2;
                ldm_x4(kh4, rb);
                ldm_x4(kl4, rb + A_SUB*2);
                #pragma unroll
                for (int sub = 0; sub < 2; sub++) {
                    float* c = s[nb*2 + sub];
                    mma_bf16(c, qh[kk], kh4[sub], kh4[sub+2]);
                    mma_bf16(c, qh[kk], kl4[sub], kl4[sub+2]);
                    mma_bf16(c, ql[kk], kh4[sub], kh4[sub+2]);
                }
            }
        }

        // ---- causal mask (diagonal tile only: kv0 == q0 tile when jt == qt) ----
        if (kv0 + 63 > wrow0) {
            #pragma unroll
            for (int nf = 0; nf < 8; nf++) {
                int c0 = kv0 + nf*8 + t2;
                if (c0     > row0)     s[nf][0] = -1e30f;
                if (c0 + 1 > row0)     s[nf][1] = -1e30f;
                if (c0     > row0 + 8) s[nf][2] = -1e30f;
                if (c0 + 1 > row0 + 8) s[nf][3] = -1e30f;
            }
        }

        // ---- online softmax ----
        float mx0 = -INFINITY, mx1 = -INFINITY;
        #pragma unroll
        for (int nf = 0; nf < 8; nf++) {
            mx0 = fmaxf(mx0, fmaxf(s[nf][0], s[nf][1]));
            mx1 = fmaxf(mx1, fmaxf(s[nf][2], s[nf][3]));
        }
        mx0 = fmaxf(mx0, __shfl_xor_sync(0xffffffffu, mx0, 1));
        mx0 = fmaxf(mx0, __shfl_xor_sync(0xffffffffu, mx0, 2));
        mx1 = fmaxf(mx1, __shfl_xor_sync(0xffffffffu, mx1, 1));
        mx1 = fmaxf(mx1, __shfl_xor_sync(0xffffffffu, mx1, 2));
        float mn0 = fmaxf(m_[0], mx0), mn1 = fmaxf(m_[1], mx1);
        float f0 = __expf(m_[0] - mn0), f1 = __expf(m_[1] - mn1);
        m_[0] = mn0; m_[1] = mn1;

        float sum0 = 0.f, sum1 = 0.f;
        #pragma unroll
        for (int nf = 0; nf < 8; nf++) {
            s[nf][0] = __expf(s[nf][0] - mn0); sum0 += s[nf][0];
            s[nf][1] = __expf(s[nf][1] - mn0); sum0 += s[nf][1];
            s[nf][2] = __expf(s[nf][2] - mn1); sum1 += s[nf][2];
            s[nf][3] = __expf(s[nf][3] - mn1); sum1 += s[nf][3];
        }
        sum0 += __shfl_xor_sync(0xffffffffu, sum0, 1);
        sum0 += __shfl_xor_sync(0xffffffffu, sum0, 2);
        sum1 += __shfl_xor_sync(0xffffffffu, sum1, 1);
        sum1 += __shfl_xor_sync(0xffffffffu, sum1, 2);
        l_[0] = l_[0] * f0 + sum0;
        l_[1] = l_[1] * f1 + sum1;

        #pragma unroll
        for (int nf = 0; nf < 16; nf++) {
            o[nf][0] *= f0; o[nf][1] *= f0;
            o[nf][2] *= f1; o[nf][3] *= f1;
        }

        // ---- pack P hi/lo as A-frags ----
        uint32_t ph[4][4], pl[4][4];
        #pragma unroll
        for (int kf = 0; kf < 4; kf++) {
            #pragma unroll
            for (int j = 0; j < 4; j++) {
                int nf = 2*kf + (j >> 1);
                int c0 = (j & 1) * 2;
                float p0 = s[nf][c0], p1 = s[nf][c0 + 1];
                __nv_bfloat16 b0 = __float2bfloat16(p0), b1 = __float2bfloat16(p1);
                __nv_bfloat162 hb; hb.x = b0; hb.y = b1;
                ph[kf][j] = *(uint32_t*)&hb;
                pl[kf][j] = packbf2(p0 - __bfloat162float(b0), p1 - __bfloat162float(b1));
            }
        }

        // ---- V(jt) ready? (group {V(jt)}; allow pending {K(jt+1)}) ----
        if (more) CP_WAIT(1); else CP_WAIT(0);
        __syncthreads();

        // ---- O += P V (3-term split) ----
        const uint32_t vbase = sb + A_VH * 2;
        const int matv = lane >> 3, jv = lane & 7;
        #pragma unroll
        for (int kf = 0; kf < 4; kf++) {
            #pragma unroll
            for (int ng = 0; ng < 8; ng++) {
                uint32_t vh4[4], vl4[4];
                uint32_t va = vbase + (uint32_t)((kf*16 + jv + ((matv & 1) << 3)) * AKVLD
                                                + ng*16 + ((matv >> 1) << 3)) * 2;
                ldm_x4_t(vh4, va);
                ldm_x4_t(vl4, va + A_SUB*2);
                #pragma unroll
                for (int sub = 0; sub < 2; sub++) {
                    float* c = o[ng*2 + sub];
                    mma_bf16(c, ph[kf], vh4[sub*2], vh4[sub*2+1]);
                    mma_bf16(c, ph[kf], vl4[sub*2], vl4[sub*2+1]);
                    mma_bf16(c, pl[kf], vh4[sub*2], vh4[sub*2+1]);
                }
            }
        }
        __syncthreads();                              // V buffer consumed by all warps
        if (more) { load_V(jt + 1); CP_COMMIT(); }    // overlapped by next S+softmax
    }

    // ---- epilogue: normalize, split bf16 hi/lo, write x-layout ----
    const float inv0 = 1.f / l_[0];
    const float inv1 = 1.f / l_[1];
    const int bb = bh >> 4, h = bh & 15;
    const size_t rA0 = (size_t)(bb * SEQLEN + row0) * D_MODEL + h * DHEAD;
    const size_t rA1 = rA0 + 8 * D_MODEL;
    #pragma unroll
    for (int nf = 0; nf < 16; nf++) {
        int d = nf*8 + t2;
        float v00 = o[nf][0]*inv0, v01 = o[nf][1]*inv0;
        float v10 = o[nf][2]*inv1, v11 = o[nf][3]*inv1;
        __nv_bfloat16 h00 = __float2bfloat16(v00), h01 = __float2bfloat16(v01);
        __nv_bfloat16 h10 = __float2bfloat16(v10), h11 = __float2bfloat16(v11);
        __nv_bfloat162 hp0; hp0.x = h00; hp0.y = h01;
        __nv_bfloat162 hp1; hp1.x = h10; hp1.y = h11;
        *(__nv_bfloat162*)(g_ahi + rA0 + d) = hp0;
        *(__nv_bfloat162*)(g_ahi + rA1 + d) = hp1;
        __nv_bfloat162 lp0, lp1;
        lp0.x = __float2bfloat16(v00 - __bfloat162float(h00));
        lp0.y = __float2bfloat16(v01 - __bfloat162float(h01));
        lp1.x = __float2bfloat16(v10 - __bfloat162float(h10));
        lp1.y = __float2bfloat16(v11 - __bfloat162float(h11));
        *(__nv_bfloat162*)(g_alo + rA0 + d) = lp0;
        *(__nv_bfloat162*)(g_alo + rA1 + d) = lp1;
    }
}

// ---------------- launch -----------------------------------------------------------
extern "C" void kernel_launch(void* const* d_in, const int* in_sizes, int n_in,
                              void* d_out, int out_size)
{
    const float* x  = (const float*)d_in[0];
    const float* Wq = (const float*)d_in[1];
    const float* bq = (const float*)d_in[2];
    const float* Wk = (const float*)d_in[3];
    const float* bk = (const float*)d_in[4];
    const float* Wv = (const float*)d_in[5];
    const float* bv = (const float*)d_in[6];
    const float* Wo = (const float*)d_in[7];
    const float* bo = (const float*)d_in[8];
    float* out = (float*)d_out;

    cudaFuncSetAttribute(attn_mma, cudaFuncAttributeMaxDynamicSharedMemorySize, SM_ATTN_BYTES);
    cudaFuncSetAttribute(qkv_mma,  cudaFuncAttributeMaxDynamicSharedMemorySize, SMEM_GEMM_BYTES);
    cudaFuncSetAttribute(out_mma,  cudaFuncAttributeMaxDynamicSharedMemorySize, SMEM_GEMM_BYTES);

    rope_table_kernel<<<512, 256>>>();

    const int NX = MROWS * D_MODEL;
    const int NW = D_MODEL * D_MODEL;
    split_x_kernel<<<NX/256, 256>>>(x);
    split_w_kernel<<<dim3(NW/256, 4), 256>>>(Wq, Wk, Wv, Wo);

    qkv_mma<<<dim3(16, 32, 3), 256, SMEM_GEMM_BYTES>>>(bq, bk, bv);

    attn_mma<<<dim3(32, 32), 128, SM_ATTN_BYTES>>>();

    out_mma<<<dim3(16, 32), 256, SMEM_GEMM_BYTES>>>(bo, out);
}